// round 8
// baseline (speedup 1.0000x reference)
#include <cuda_runtime.h>
#include <cuda_fp16.h>
#include <cuda_bf16.h>
#include <math.h>

#define NN 1024
#define NPG 128
#define NB 8
#define KM 64
#define H 600
#define G 50
#define NL 6
#define NC 259           // coarse knots, d=(q-1)*D0, q=0..258
#define D0 (10.0f/256.0f)
#define PF 4096          // fine intervals over [0,10]
#define PFP1 4097
#define K2 1824          // split-K' = 3*600 padded to multiple of 32 (57 iters)
#define NIT 57

// ---------------- device scratch (zero-initialized at module load) ----------------
__device__ float g_h[NN*H];
__device__ __half g_x1h[NN*H];
__device__ __nv_bfloat16 g_As0[(size_t)NN*K2];   // h split
__device__ __nv_bfloat16 g_As1[(size_t)NN*K2];   // msg split
__device__ __nv_bfloat16 g_As2[(size_t)NN*K2];   // m1 split
__device__ __nv_bfloat16 g_Bw[(size_t)18*K2*H];  // weight splits (lin1,l2w,ilw per layer)
__device__ float g_T[NL*NC*H], g_tmp[NL*NC*H], g_ea[NC*G], g_C[NC];
__device__ __half g_fine[(size_t)NL*PFP1*H];     // ~29.5 MB
__device__ float g_pool[NB*H];
__device__ int   g_nbr[NN*KM], g_base[NN*KM], g_cnt[NN];
__device__ float g_w1f[NN*KM];

__device__ __forceinline__ float sspf(float x){
    float r = (x > 0.f) ? (x + log1pf(expf(-x))) : log1pf(expf(x));
    return r - 0.69314718055994530942f;
}

__device__ __forceinline__ void split_store(__nv_bfloat16* base, size_t off,
                                            float v0, float v1){
    __nv_bfloat16 h0=__float2bfloat16(v0), h1=__float2bfloat16(v1);
    __nv_bfloat162 hi2; hi2.x=h0; hi2.y=h1;
    __nv_bfloat162 lo2;
    lo2.x=__float2bfloat16(v0-__bfloat162float(h0));
    lo2.y=__float2bfloat16(v1-__bfloat162float(h1));
    __nv_bfloat162* dp = reinterpret_cast<__nv_bfloat162*>(base + off);
    dp[0]   = hi2;     // k = c      (A_hi)
    dp[300] = hi2;     // k = 600+c  (A_hi)
    dp[600] = lo2;     // k = 1200+c (A_lo)
}

// ---- graph build: 1 block per node, matches jax top_k(-dist2, K) ----
__global__ void build_graph(const float* __restrict__ pos){
    int i = blockIdx.x, b = i/NPG, il = i - b*NPG, j = threadIdx.x;
    __shared__ float sx[NPG], sy[NPG], sz[NPG], sd2[NPG];
    __shared__ int scnt;
    const float* pg = pos + (size_t)b*NPG*3;
    sx[j]=pg[j*3]; sy[j]=pg[j*3+1]; sz[j]=pg[j*3+2];
    if(j==0) scnt=0;
    __syncthreads();
    float dx=__fsub_rn(sx[il],sx[j]), dy=__fsub_rn(sy[il],sy[j]), dz=__fsub_rn(sz[il],sz[j]);
    float d2=__fadd_rn(__fadd_rn(__fmul_rn(dx,dx),__fmul_rn(dy,dy)),__fmul_rn(dz,dz));
    bool ok = (d2<=100.0f) && (j!=il);
    sd2[j] = ok ? d2 : 3.0e38f;
    __syncthreads();
    int rank=0;
    if(ok){
        #pragma unroll 8
        for(int t=0;t<NPG;t++){ float o=sd2[t]; rank += (o<d2)||(o==d2 && t<j); }
        atomicAdd(&scnt,1);
    }
    __syncthreads();
    if(j==0) g_cnt[i] = min(scnt,KM);
    if(ok && rank<KM){
        float d = sqrtf(d2);
        float u = d * ((float)PF / 10.0f);
        int p = (int)u; if(p > PF-1) p = PF-1; if(p < 0) p = 0;
        int e=i*KM+rank;
        g_nbr[e]=b*NPG+j;
        g_base[e]=p*H;
        g_w1f[e]=u-(float)p;
    }
}

// ---- gaussian smearing + cosine cutoff on coarse grid ----
__global__ void smear(){
    int idx = blockIdx.x*blockDim.x + threadIdx.x;
    if(idx >= NC*G) return;
    int q = idx/G, g = idx - q*G;
    float d = (float)(q-1)*D0;
    float step = 10.0f/49.0f;
    float x = d - (float)g*step;
    g_ea[idx] = expf((-0.5f/(step*step))*x*x);
    if(g==0) g_C[q] = 0.5f*(cosf(d*0.31415926535897932f)+1.0f);
}

// ---- embedding gather + h split ----
__global__ void embed(const float* __restrict__ emb, const int* __restrict__ z){
    int idx = blockIdx.x*blockDim.x + threadIdx.x;
    if(idx >= NN*H) return;
    int i = idx/H, c = idx - i*H;
    float v = emb[z[i]*H + c];
    g_h[idx] = v;
    __nv_bfloat16 hi = __float2bfloat16(v);
    g_As0[(size_t)i*K2 + c]        = hi;
    g_As0[(size_t)i*K2 + 600 + c]  = hi;
    g_As0[(size_t)i*K2 + 1200 + c] = __float2bfloat16(v - __bfloat162float(hi));
}

// ---- weight split: 18 [600,600] fp32 -> [1824,600] bf16 (hi|lo|hi rows) ----
__global__ void wsplit(const float* __restrict__ lin1, const float* __restrict__ l2w,
                       const float* __restrict__ ilw){
    int idx = blockIdx.x*blockDim.x + threadIdx.x;
    if(idx >= 18*H*H) return;
    int w = idx/(H*H), e = idx - w*(H*H), r = e/H, c = e - r*H;
    int l = w/3, kind = w - l*3;
    const float* src = (kind==0) ? lin1 : (kind==1) ? l2w : ilw;
    float v = src[(size_t)l*H*H + e];
    __nv_bfloat16 hi = __float2bfloat16(v);
    __nv_bfloat16* dst = g_Bw + (size_t)w*K2*H;
    dst[(size_t)r*H + c]          = hi;
    dst[(size_t)(600+r)*H + c]    = __float2bfloat16(v - __bfloat162float(hi));
    dst[(size_t)(1200+r)*H + c]   = hi;
}

// ---- 16x Catmull-Rom upsample coarse fp32 -> fine fp16 ----
__global__ void upsample(){
    int idx = blockIdx.x*blockDim.x + threadIdx.x;
    if(idx >= PFP1*H) return;
    int l = blockIdx.y;
    int f = idx / H;
    int h = idx - f*H;
    int s = f >> 4; if(s > 255) s = 255;
    float t = (float)(f - (s<<4)) * (1.0f/16.0f);
    const float* c = g_T + (size_t)l*NC*H + (size_t)s*H + h;
    float p0=c[0], p1=c[H], p2=c[2*H], p3=c[3*H];
    float bq = p2 - p0;
    float cq = 2.f*p0 - 5.f*p1 + 4.f*p2 - p3;
    float dq = 3.f*(p1 - p2) + p3 - p0;
    float v = 0.5f*(2.f*p1 + t*(bq + t*(cq + t*dq)));
    g_fine[(size_t)l*PFP1*H + idx] = __float2half_rn(v);
}

// ---- aggregation: linear interp fp16 fine table * fp16 x1; emits msg split ----
__global__ void __launch_bounds__(320) agg(int l){
    int i = blockIdx.x, t = threadIdx.x;
    __shared__ int s_j[KM], s_b[KM], s_cnt;
    __shared__ float s_w[KM];
    if(t==0) s_cnt = g_cnt[i];
    if(t<KM){
        int e=i*KM+t;
        s_j[t]=g_nbr[e]*H; s_b[t]=g_base[e]; s_w[t]=g_w1f[e];
    }
    __syncthreads();
    if(t >= 300) return;
    int h = t*2;
    const __half* T = g_fine + (size_t)l*PFP1*H;
    int cnt = s_cnt;
    float ax = 0.f, ay = 0.f;
    #pragma unroll 4
    for(int k=0;k<cnt;k++){
        const __half2* tp = reinterpret_cast<const __half2*>(T + s_b[k] + h);
        float2 t0=__half22float2(__ldg(tp));
        float2 t1=__half22float2(__ldg(tp+300));
        float2 x2=__half22float2(__ldg(reinterpret_cast<const __half2*>(&g_x1h[s_j[k]+h])));
        float w = s_w[k];
        float vx = fmaf(w, t1.x - t0.x, t0.x);
        float vy = fmaf(w, t1.y - t0.y, t0.y);
        ax = fmaf(vx, x2.x, ax);
        ay = fmaf(vy, x2.y, ay);
    }
    split_store(g_As1, (size_t)i*K2 + h, ax, ay);
}

// ---- mma helpers ----
__device__ __forceinline__ void ldsm4(unsigned* r, unsigned addr){
    asm volatile("ldmatrix.sync.aligned.m8n8.x4.shared.b16 {%0,%1,%2,%3}, [%4];"
        : "=r"(r[0]),"=r"(r[1]),"=r"(r[2]),"=r"(r[3]) : "r"(addr));
}
__device__ __forceinline__ void ldsm4t(unsigned* r, unsigned addr){
    asm volatile("ldmatrix.sync.aligned.m8n8.x4.trans.shared.b16 {%0,%1,%2,%3}, [%4];"
        : "=r"(r[0]),"=r"(r[1]),"=r"(r[2]),"=r"(r[3]) : "r"(addr));
}
__device__ __forceinline__ void mma16816(float* c, const unsigned* a, unsigned b0, unsigned b1){
    asm volatile("mma.sync.aligned.m16n8k16.row.col.f32.bf16.bf16.f32 "
        "{%0,%1,%2,%3}, {%4,%5,%6,%7}, {%8,%9}, {%0,%1,%2,%3};"
        : "+f"(c[0]),"+f"(c[1]),"+f"(c[2]),"+f"(c[3])
        : "r"(a[0]),"r"(a[1]),"r"(a[2]),"r"(a[3]), "r"(b0),"r"(b1));
}

// ---- bf16 split GEMM: C[1024,600] = A'[1024,1824] @ B'[1824,600], fused epilogue ----
// EPI 0: -> x1h fp16 (no bias). EPI 1: ssp(+bias) -> split sout. EPI 2: +bias+h residual -> h & split sout.
template<int EPI>
__global__ void __launch_bounds__(128) bgemm(const __nv_bfloat16* __restrict__ Ap,
        const __nv_bfloat16* __restrict__ Bp, const float* __restrict__ bias,
        float* __restrict__ hbuf, __nv_bfloat16* __restrict__ sout,
        __half* __restrict__ x1out){
    __shared__ __nv_bfloat16 As[64][40];   // [m][k], pad to 80B rows
    __shared__ __nv_bfloat16 Bs[32][72];   // [k][n], pad to 144B rows
    int tid = threadIdx.x;
    int m0 = blockIdx.y*64, n0 = blockIdx.x*64;
    int warp = tid>>5, lane = tid&31;
    int wm = (warp>>1)*32, wn = (warp&1)*32;

    int arow[2], acol[2], brow[2], bcol[2]; bool bok[2];
    #pragma unroll
    for(int p=0;p<2;p++){
        int c = p*128 + tid;
        arow[p]=c>>2;  acol[p]=(c&3)*8;
        brow[p]=c>>3;  bcol[p]=(c&7)*8;
        bok[p] = (n0 + bcol[p] + 8) <= 600;
    }

    unsigned aaddr[2][2], baddr[2][2];
    #pragma unroll
    for(int mi=0;mi<2;mi++)
        #pragma unroll
        for(int s=0;s<2;s++)
            aaddr[mi][s] = (unsigned)__cvta_generic_to_shared(
                &As[wm + mi*16 + (lane&15)][s*16 + (lane>>4)*8]);
    #pragma unroll
    for(int nh=0;nh<2;nh++)
        #pragma unroll
        for(int s=0;s<2;s++)
            baddr[nh][s] = (unsigned)__cvta_generic_to_shared(
                &Bs[s*16 + (lane&15)][wn + nh*16 + (lane>>4)*8]);

    float acc[2][4][4];
    #pragma unroll
    for(int mi=0;mi<2;mi++)
        #pragma unroll
        for(int ni=0;ni<4;ni++)
            #pragma unroll
            for(int q=0;q<4;q++) acc[mi][ni][q]=0.f;

    uint4 ar[2], br[2];
    #pragma unroll
    for(int p=0;p<2;p++){
        ar[p] = *reinterpret_cast<const uint4*>(Ap + (size_t)(m0+arow[p])*K2 + acol[p]);
        br[p] = bok[p] ? *reinterpret_cast<const uint4*>(Bp + (size_t)brow[p]*H + n0 + bcol[p])
                       : make_uint4(0,0,0,0);
    }
    #pragma unroll
    for(int p=0;p<2;p++){
        *reinterpret_cast<uint4*>(&As[arow[p]][acol[p]]) = ar[p];
        *reinterpret_cast<uint4*>(&Bs[brow[p]][bcol[p]]) = br[p];
    }
    __syncthreads();

    for(int it=0; it<NIT; it++){
        int k1 = (it+1)*32;
        if(it+1 < NIT){
            #pragma unroll
            for(int p=0;p<2;p++){
                ar[p] = *reinterpret_cast<const uint4*>(Ap + (size_t)(m0+arow[p])*K2 + k1 + acol[p]);
                br[p] = bok[p] ? *reinterpret_cast<const uint4*>(Bp + (size_t)(k1+brow[p])*H + n0 + bcol[p])
                               : make_uint4(0,0,0,0);
            }
        }
        #pragma unroll
        for(int s=0;s<2;s++){
            unsigned af[2][4], bf[2][4];
            ldsm4 (af[0], aaddr[0][s]);
            ldsm4 (af[1], aaddr[1][s]);
            ldsm4t(bf[0], baddr[0][s]);
            ldsm4t(bf[1], baddr[1][s]);
            #pragma unroll
            for(int mi=0;mi<2;mi++)
                #pragma unroll
                for(int ni=0;ni<4;ni++){
                    const unsigned* bp = &bf[ni>>1][(ni&1)*2];
                    mma16816(acc[mi][ni], af[mi], bp[0], bp[1]);
                }
        }
        __syncthreads();
        if(it+1 < NIT){
            #pragma unroll
            for(int p=0;p<2;p++){
                *reinterpret_cast<uint4*>(&As[arow[p]][acol[p]]) = ar[p];
                *reinterpret_cast<uint4*>(&Bs[brow[p]][bcol[p]]) = br[p];
            }
            __syncthreads();
        }
    }

    // epilogue
    #pragma unroll
    for(int mi=0;mi<2;mi++){
        #pragma unroll
        for(int ni=0;ni<4;ni++){
            int c0 = n0 + wn + ni*8 + (lane&3)*2;
            if(c0 >= 600) continue;
            #pragma unroll
            for(int hf=0; hf<2; hf++){
                int r = m0 + wm + mi*16 + (lane>>2) + hf*8;
                float v0 = acc[mi][ni][hf*2], v1 = acc[mi][ni][hf*2+1];
                if(EPI==0){
                    *reinterpret_cast<__half2*>(x1out + (size_t)r*H + c0)
                        = __floats2half2_rn(v0, v1);
                } else {
                    v0 += bias[c0]; v1 += bias[c0+1];
                    if(EPI==1){
                        v0 = sspf(v0); v1 = sspf(v1);
                    } else {
                        float2 hv = *reinterpret_cast<float2*>(hbuf + (size_t)r*H + c0);
                        v0 += hv.x; v1 += hv.y;
                        *reinterpret_cast<float2*>(hbuf + (size_t)r*H + c0) = make_float2(v0, v1);
                    }
                    split_store(sout, (size_t)r*K2 + c0, v0, v1);
                }
            }
        }
    }
}

// ---- batched SIMT fp32 GEMM for table build (small, exact) ----
// EPI: 1 ssp, 3 *=extra[m]
template<int EPI>
__global__ void __launch_bounds__(256) sgemm_b(const float* A, const float* B,
        const float* bias, const float* extra, float* Cm,
        int M, int N, int K, long sA, long sB, long sb, long sC){
    int zb = blockIdx.z;
    A  += (size_t)zb * sA;
    B  += (size_t)zb * sB;
    Cm += (size_t)zb * sC;
    if(bias) bias += (size_t)zb * sb;

    const int BM=64, BN=64, BK=16;
    __shared__ float As[BK][BM], Bs[BK][BN];
    int tid=threadIdx.x, tx=tid&15, ty=tid>>4;
    int m0=blockIdx.y*BM, n0=blockIdx.x*BN;
    int ar=tid>>2, ac=(tid&3)<<2, br=tid>>4, bc=(tid&15)<<2;
    float acc[4][4];
    #pragma unroll
    for(int a=0;a<4;a++)
        #pragma unroll
        for(int c=0;c<4;c++) acc[a][c]=0.f;
    for(int k0=0;k0<K;k0+=BK){
        int gm=m0+ar;
        #pragma unroll
        for(int u=0;u<4;u++){
            int gk=k0+ac+u;
            As[ac+u][ar] = (gm<M && gk<K) ? A[(size_t)gm*K+gk] : 0.f;
        }
        int gk2=k0+br;
        #pragma unroll
        for(int u=0;u<4;u++){
            int gn=n0+bc+u;
            Bs[br][bc+u] = (gk2<K && gn<N) ? B[(size_t)gk2*N+gn] : 0.f;
        }
        __syncthreads();
        #pragma unroll
        for(int kk=0;kk<BK;kk++){
            float4 av=*reinterpret_cast<const float4*>(&As[kk][ty<<2]);
            float4 bv=*reinterpret_cast<const float4*>(&Bs[kk][tx<<2]);
            float a0=av.x,a1=av.y,a2=av.z,a3=av.w;
            float b0=bv.x,b1=bv.y,b2=bv.z,b3=bv.w;
            acc[0][0]=fmaf(a0,b0,acc[0][0]); acc[0][1]=fmaf(a0,b1,acc[0][1]);
            acc[0][2]=fmaf(a0,b2,acc[0][2]); acc[0][3]=fmaf(a0,b3,acc[0][3]);
            acc[1][0]=fmaf(a1,b0,acc[1][0]); acc[1][1]=fmaf(a1,b1,acc[1][1]);
            acc[1][2]=fmaf(a1,b2,acc[1][2]); acc[1][3]=fmaf(a1,b3,acc[1][3]);
            acc[2][0]=fmaf(a2,b0,acc[2][0]); acc[2][1]=fmaf(a2,b1,acc[2][1]);
            acc[2][2]=fmaf(a2,b2,acc[2][2]); acc[2][3]=fmaf(a2,b3,acc[2][3]);
            acc[3][0]=fmaf(a3,b0,acc[3][0]); acc[3][1]=fmaf(a3,b1,acc[3][1]);
            acc[3][2]=fmaf(a3,b2,acc[3][2]); acc[3][3]=fmaf(a3,b3,acc[3][3]);
        }
        __syncthreads();
    }
    #pragma unroll
    for(int ii=0;ii<4;ii++){
        int m=m0+(ty<<2)+ii;
        if(m>=M) continue;
        #pragma unroll
        for(int jj=0;jj<4;jj++){
            int n=n0+(tx<<2)+jj;
            if(n>=N) continue;
            float v=acc[ii][jj];
            if(bias) v += bias[n];
            if(EPI==1) v = sspf(v);
            else if(EPI==3) v *= extra[m];
            Cm[(size_t)m*N+n]=v;
        }
    }
}

__global__ void pool(){
    int idx = blockIdx.x*blockDim.x + threadIdx.x;
    if(idx >= NB*H) return;
    int b = idx/H, h = idx - b*H;
    const float* p = g_h + (size_t)b*NPG*H + h;
    float s = 0.f;
    #pragma unroll 8
    for(int n=0;n<NPG;n++) s += p[(size_t)n*H];
    g_pool[idx] = s * (1.0f/NPG);
}

__global__ void final_lin(const float* __restrict__ pw, const float* __restrict__ pb,
                          float* __restrict__ out){
    int idx = blockIdx.x*blockDim.x + threadIdx.x;
    if(idx >= NB*H) return;
    int b = idx/H, n = idx - b*H;
    const float* pr = g_pool + b*H;
    float s = pb[n];
    for(int k=0;k<H;k++) s = fmaf(pr[k], pw[(size_t)k*H+n], s);
    out[idx] = s;
}

extern "C" void kernel_launch(void* const* d_in, const int* in_sizes, int n_in,
                              void* d_out, int out_size){
    // dict order: z,pos,emb,w1,b1,w2,b2,lin1,l2w,l2b,ilw,ilb,pw,pb
    int map[14] = {0,1,2,3,4,5,6,7,8,9,10,11,12,13};
    if(!(in_sizes[0]==1024 && in_sizes[1]==3072)){
        int sig[14] = {13,0,1,2,3,4,5,6,7,8,9,10,11,12};
        for(int i=0;i<14;i++) map[i]=sig[i];
    }
    const int*   z    = (const int*)  d_in[map[0]];
    const float* posv = (const float*)d_in[map[1]];
    const float* emb  = (const float*)d_in[map[2]];
    const float* w1   = (const float*)d_in[map[3]];
    const float* b1   = (const float*)d_in[map[4]];
    const float* w2   = (const float*)d_in[map[5]];
    const float* b2   = (const float*)d_in[map[6]];
    const float* lin1 = (const float*)d_in[map[7]];
    const float* l2w  = (const float*)d_in[map[8]];
    const float* l2b  = (const float*)d_in[map[9]];
    const float* ilw  = (const float*)d_in[map[10]];
    const float* ilb  = (const float*)d_in[map[11]];
    const float* pw   = (const float*)d_in[map[12]];
    const float* pb   = (const float*)d_in[map[13]];
    float* out = (float*)d_out;

    float *p_h,*p_T,*p_tmp,*p_ea,*p_C;
    __nv_bfloat16 *p_As0,*p_As1,*p_As2,*p_Bw;
    __half *p_x1h;
    cudaGetSymbolAddress((void**)&p_h,   g_h);
    cudaGetSymbolAddress((void**)&p_T,   g_T);
    cudaGetSymbolAddress((void**)&p_tmp, g_tmp);
    cudaGetSymbolAddress((void**)&p_ea,  g_ea);
    cudaGetSymbolAddress((void**)&p_C,   g_C);
    cudaGetSymbolAddress((void**)&p_As0, g_As0);
    cudaGetSymbolAddress((void**)&p_As1, g_As1);
    cudaGetSymbolAddress((void**)&p_As2, g_As2);
    cudaGetSymbolAddress((void**)&p_Bw,  g_Bw);
    cudaGetSymbolAddress((void**)&p_x1h, g_x1h);

    build_graph<<<NN, NPG>>>(posv);
    smear<<<(NC*G+255)/256, 256>>>();
    embed<<<(NN*H+255)/256, 256>>>(emb, z);
    wsplit<<<(18*H*H+255)/256, 256>>>(lin1, l2w, ilw);

    // coarse filter tables (exact fp32) then fine fp16 upsample
    dim3 gT((H+63)/64, (NC+63)/64, NL);
    sgemm_b<1><<<gT,256>>>(p_ea, w1, b1, nullptr, p_tmp,
                           NC, H, G, 0L, (long)G*H, (long)H, (long)NC*H);
    sgemm_b<3><<<gT,256>>>(p_tmp, w2, b2, p_C, p_T,
                           NC, H, H, (long)NC*H, (long)H*H, (long)H, (long)NC*H);
    dim3 gU((PFP1*H+255)/256, NL);
    upsample<<<gU, 256>>>();

    dim3 gG(10, 16);   // n-tiles x m-tiles
    for(int l=0;l<NL;l++){
        const __nv_bfloat16* Blin1 = p_Bw + (size_t)(l*3+0)*K2*H;
        const __nv_bfloat16* Bl2w  = p_Bw + (size_t)(l*3+1)*K2*H;
        const __nv_bfloat16* Bilw  = p_Bw + (size_t)(l*3+2)*K2*H;
        // x1 = h @ lin1 -> fp16
        bgemm<0><<<gG,128>>>(p_As0, Blin1, nullptr, nullptr, nullptr, p_x1h);
        // msg (split) from neighbor aggregation
        agg<<<NN, 320>>>(l);
        // m1 = ssp(msg @ l2w + l2b) -> split
        bgemm<1><<<gG,128>>>(p_As1, Bl2w, l2b+(size_t)l*H, nullptr, p_As2, nullptr);
        // h = h + (m1 @ ilw + ilb); emits h split for next layer
        bgemm<2><<<gG,128>>>(p_As2, Bilw, ilb+(size_t)l*H, p_h, p_As0, nullptr);
    }
    pool<<<(NB*H+255)/256, 256>>>();
    final_lin<<<(NB*H+255)/256, 256>>>(pw, pb, out);
}

// round 9
// speedup vs baseline: 1.2136x; 1.2136x over previous
#include <cuda_runtime.h>
#include <cuda_fp16.h>
#include <cuda_bf16.h>
#include <math.h>

#define NN 1024
#define NPG 128
#define NB 8
#define KM 64
#define H 600
#define G 50
#define NL 6
#define NC 259           // coarse knots, d=(q-1)*D0, q=0..258
#define D0 (10.0f/256.0f)
#define PF 4096          // fine intervals over [0,10]
#define PFP1 4097
#define K2 1824          // split-K' = 3*600 padded to multiple of 32 (57 iters)
#define NIT 57

// ---------------- device scratch (zero-initialized at module load) ----------------
__device__ float g_h[NN*H];
__device__ __half g_x1h[NN*H];
__device__ __nv_bfloat16 g_As0[(size_t)NN*K2];   // h split
__device__ __nv_bfloat16 g_As1[(size_t)NN*K2];   // msg split
__device__ __nv_bfloat16 g_As2[(size_t)NN*K2];   // m1 split
__device__ __nv_bfloat16 g_Bw[(size_t)18*K2*H];  // weight splits (lin1,l2w,ilw per layer)
__device__ float g_T[NL*NC*H], g_tmp[NL*NC*H], g_ea[NC*G], g_C[NC];
__device__ __half g_fine[(size_t)NL*PFP1*H];     // ~29.5 MB
__device__ float g_pool[NB*H];
__device__ int   g_nbr[NN*KM], g_base[NN*KM], g_cnt[NN];
__device__ float g_w1f[NN*KM];

__device__ __forceinline__ float sspf(float x){
    float r = (x > 0.f) ? (x + log1pf(expf(-x))) : log1pf(expf(x));
    return r - 0.69314718055994530942f;
}

__device__ __forceinline__ void split_store(__nv_bfloat16* base, size_t off,
                                            float v0, float v1){
    __nv_bfloat16 h0=__float2bfloat16(v0), h1=__float2bfloat16(v1);
    __nv_bfloat162 hi2; hi2.x=h0; hi2.y=h1;
    __nv_bfloat162 lo2;
    lo2.x=__float2bfloat16(v0-__bfloat162float(h0));
    lo2.y=__float2bfloat16(v1-__bfloat162float(h1));
    __nv_bfloat162* dp = reinterpret_cast<__nv_bfloat162*>(base + off);
    dp[0]   = hi2;     // k = c      (A_hi)
    dp[300] = hi2;     // k = 600+c  (A_hi)
    dp[600] = lo2;     // k = 1200+c (A_lo)
}

// ---- graph build: 1 block per node, matches jax top_k(-dist2, K) ----
__global__ void build_graph(const float* __restrict__ pos){
    int i = blockIdx.x, b = i/NPG, il = i - b*NPG, j = threadIdx.x;
    __shared__ float sx[NPG], sy[NPG], sz[NPG], sd2[NPG];
    __shared__ int scnt;
    const float* pg = pos + (size_t)b*NPG*3;
    sx[j]=pg[j*3]; sy[j]=pg[j*3+1]; sz[j]=pg[j*3+2];
    if(j==0) scnt=0;
    __syncthreads();
    float dx=__fsub_rn(sx[il],sx[j]), dy=__fsub_rn(sy[il],sy[j]), dz=__fsub_rn(sz[il],sz[j]);
    float d2=__fadd_rn(__fadd_rn(__fmul_rn(dx,dx),__fmul_rn(dy,dy)),__fmul_rn(dz,dz));
    bool ok = (d2<=100.0f) && (j!=il);
    sd2[j] = ok ? d2 : 3.0e38f;
    __syncthreads();
    int rank=0;
    if(ok){
        #pragma unroll 8
        for(int t=0;t<NPG;t++){ float o=sd2[t]; rank += (o<d2)||(o==d2 && t<j); }
        atomicAdd(&scnt,1);
    }
    __syncthreads();
    if(j==0) g_cnt[i] = min(scnt,KM);
    if(ok && rank<KM){
        float d = sqrtf(d2);
        float u = d * ((float)PF / 10.0f);
        int p = (int)u; if(p > PF-1) p = PF-1; if(p < 0) p = 0;
        int e=i*KM+rank;
        g_nbr[e]=b*NPG+j;
        g_base[e]=p*H;
        g_w1f[e]=u-(float)p;
    }
}

// ---- gaussian smearing + cosine cutoff on coarse grid ----
__global__ void smear(){
    int idx = blockIdx.x*blockDim.x + threadIdx.x;
    if(idx >= NC*G) return;
    int q = idx/G, g = idx - q*G;
    float d = (float)(q-1)*D0;
    float step = 10.0f/49.0f;
    float x = d - (float)g*step;
    g_ea[idx] = expf((-0.5f/(step*step))*x*x);
    if(g==0) g_C[q] = 0.5f*(cosf(d*0.31415926535897932f)+1.0f);
}

// ---- embedding gather + h split ----
__global__ void embed(const float* __restrict__ emb, const int* __restrict__ z){
    int idx = blockIdx.x*blockDim.x + threadIdx.x;
    if(idx >= NN*H) return;
    int i = idx/H, c = idx - i*H;
    float v = emb[z[i]*H + c];
    g_h[idx] = v;
    __nv_bfloat16 hi = __float2bfloat16(v);
    g_As0[(size_t)i*K2 + c]        = hi;
    g_As0[(size_t)i*K2 + 600 + c]  = hi;
    g_As0[(size_t)i*K2 + 1200 + c] = __float2bfloat16(v - __bfloat162float(hi));
}

// ---- weight split: 18 [600,600] fp32 -> [1824,600] bf16 (hi|lo|hi rows) ----
__global__ void wsplit(const float* __restrict__ lin1, const float* __restrict__ l2w,
                       const float* __restrict__ ilw){
    int idx = blockIdx.x*blockDim.x + threadIdx.x;
    if(idx >= 18*H*H) return;
    int w = idx/(H*H), e = idx - w*(H*H), r = e/H, c = e - r*H;
    int l = w/3, kind = w - l*3;
    const float* src = (kind==0) ? lin1 : (kind==1) ? l2w : ilw;
    float v = src[(size_t)l*H*H + e];
    __nv_bfloat16 hi = __float2bfloat16(v);
    __nv_bfloat16* dst = g_Bw + (size_t)w*K2*H;
    dst[(size_t)r*H + c]          = hi;
    dst[(size_t)(600+r)*H + c]    = __float2bfloat16(v - __bfloat162float(hi));
    dst[(size_t)(1200+r)*H + c]   = hi;
}

// ---- 16x Catmull-Rom upsample coarse fp32 -> fine fp16 ----
__global__ void upsample(){
    int idx = blockIdx.x*blockDim.x + threadIdx.x;
    if(idx >= PFP1*H) return;
    int l = blockIdx.y;
    int f = idx / H;
    int h = idx - f*H;
    int s = f >> 4; if(s > 255) s = 255;
    float t = (float)(f - (s<<4)) * (1.0f/16.0f);
    const float* c = g_T + (size_t)l*NC*H + (size_t)s*H + h;
    float p0=c[0], p1=c[H], p2=c[2*H], p3=c[3*H];
    float bq = p2 - p0;
    float cq = 2.f*p0 - 5.f*p1 + 4.f*p2 - p3;
    float dq = 3.f*(p1 - p2) + p3 - p0;
    float v = 0.5f*(2.f*p1 + t*(bq + t*(cq + t*dq)));
    g_fine[(size_t)l*PFP1*H + idx] = __float2half_rn(v);
}

// ---- aggregation: linear interp fp16 fine table * fp16 x1; emits msg split ----
__global__ void __launch_bounds__(320) agg(int l){
    int i = blockIdx.x, t = threadIdx.x;
    __shared__ int s_j[KM], s_b[KM], s_cnt;
    __shared__ float s_w[KM];
    if(t==0) s_cnt = g_cnt[i];
    if(t<KM){
        int e=i*KM+t;
        s_j[t]=g_nbr[e]*H; s_b[t]=g_base[e]; s_w[t]=g_w1f[e];
    }
    __syncthreads();
    if(t >= 300) return;
    int h = t*2;
    const __half* T = g_fine + (size_t)l*PFP1*H;
    int cnt = s_cnt;
    float ax = 0.f, ay = 0.f;
    #pragma unroll 4
    for(int k=0;k<cnt;k++){
        const __half2* tp = reinterpret_cast<const __half2*>(T + s_b[k] + h);
        float2 t0=__half22float2(__ldg(tp));
        float2 t1=__half22float2(__ldg(tp+300));
        float2 x2=__half22float2(__ldg(reinterpret_cast<const __half2*>(&g_x1h[s_j[k]+h])));
        float w = s_w[k];
        float vx = fmaf(w, t1.x - t0.x, t0.x);
        float vy = fmaf(w, t1.y - t0.y, t0.y);
        ax = fmaf(vx, x2.x, ax);
        ay = fmaf(vy, x2.y, ay);
    }
    split_store(g_As1, (size_t)i*K2 + h, ax, ay);
}

// ---- mma helpers ----
__device__ __forceinline__ void ldsm4(unsigned* r, unsigned addr){
    asm volatile("ldmatrix.sync.aligned.m8n8.x4.shared.b16 {%0,%1,%2,%3}, [%4];"
        : "=r"(r[0]),"=r"(r[1]),"=r"(r[2]),"=r"(r[3]) : "r"(addr));
}
__device__ __forceinline__ void ldsm4t(unsigned* r, unsigned addr){
    asm volatile("ldmatrix.sync.aligned.m8n8.x4.trans.shared.b16 {%0,%1,%2,%3}, [%4];"
        : "=r"(r[0]),"=r"(r[1]),"=r"(r[2]),"=r"(r[3]) : "r"(addr));
}
__device__ __forceinline__ void mma16816(float* c, const unsigned* a, unsigned b0, unsigned b1){
    asm volatile("mma.sync.aligned.m16n8k16.row.col.f32.bf16.bf16.f32 "
        "{%0,%1,%2,%3}, {%4,%5,%6,%7}, {%8,%9}, {%0,%1,%2,%3};"
        : "+f"(c[0]),"+f"(c[1]),"+f"(c[2]),"+f"(c[3])
        : "r"(a[0]),"r"(a[1]),"r"(a[2]),"r"(a[3]), "r"(b0),"r"(b1));
}

#define AS_STRIDE (64*40*2)   // bytes per A stage
#define BS_STRIDE (32*72*2)   // bytes per B stage

// ---- bf16 split GEMM: C[1024,600] = A'[1024,1824] @ B'[1824,600], fused epilogue ----
// 256 threads, 8 warps (2m x 4n), warp tile 32x16, ping-pong smem, 1 sync/iter.
// EPI 0: -> x1h fp16 (no bias). EPI 1: ssp(+bias) -> split sout. EPI 2: +bias+h residual -> h & split sout.
template<int EPI>
__global__ void __launch_bounds__(256) bgemm(const __nv_bfloat16* __restrict__ Ap,
        const __nv_bfloat16* __restrict__ Bp, const float* __restrict__ bias,
        float* __restrict__ hbuf, __nv_bfloat16* __restrict__ sout,
        __half* __restrict__ x1out){
    __shared__ __nv_bfloat16 As[2][64][40];   // [stage][m][k]
    __shared__ __nv_bfloat16 Bs[2][32][72];   // [stage][k][n]
    int tid = threadIdx.x;
    int m0 = blockIdx.y*64, n0 = blockIdx.x*64;
    int warp = tid>>5, lane = tid&31;
    int wm = (warp>>2)*32;       // 0 or 32
    int wn = (warp&3)*16;        // 0,16,32,48

    // global load mapping: one uint4 A + one uint4 B per thread per stage
    int arow = tid>>2,  acol = (tid&3)*8;    // 64 x 32
    int brow = tid>>3,  bcol = (tid&7)*8;    // 32 x 64
    bool bok = (n0 + bcol + 8) <= 600;

    // fragment smem addresses (stage 0); add stg*STRIDE at use
    unsigned aaddr[2][2], baddr[2];
    #pragma unroll
    for(int mi=0;mi<2;mi++)
        #pragma unroll
        for(int s=0;s<2;s++)
            aaddr[mi][s] = (unsigned)__cvta_generic_to_shared(
                &As[0][wm + mi*16 + (lane&15)][s*16 + (lane>>4)*8]);
    #pragma unroll
    for(int s=0;s<2;s++)
        baddr[s] = (unsigned)__cvta_generic_to_shared(
            &Bs[0][s*16 + (lane&15)][wn + (lane>>4)*8]);

    float acc[2][2][4];
    #pragma unroll
    for(int mi=0;mi<2;mi++)
        #pragma unroll
        for(int ni=0;ni<2;ni++)
            #pragma unroll
            for(int q=0;q<4;q++) acc[mi][ni][q]=0.f;

    const __nv_bfloat16* aptr = Ap + (size_t)(m0+arow)*K2 + acol;
    const __nv_bfloat16* bptr = Bp + (size_t)brow*H + n0 + bcol;

    // preload stage 0
    uint4 ar = *reinterpret_cast<const uint4*>(aptr);
    uint4 br = bok ? *reinterpret_cast<const uint4*>(bptr) : make_uint4(0,0,0,0);
    *reinterpret_cast<uint4*>(&As[0][arow][acol]) = ar;
    *reinterpret_cast<uint4*>(&Bs[0][brow][bcol]) = br;
    __syncthreads();

    int stg = 0;
    for(int it=0; it<NIT; it++){
        if(it+1 < NIT){
            int k1 = (it+1)*32;
            ar = *reinterpret_cast<const uint4*>(aptr + k1);
            br = bok ? *reinterpret_cast<const uint4*>(bptr + (size_t)k1*H) : make_uint4(0,0,0,0);
        }
        unsigned aoff = stg ? AS_STRIDE : 0u;
        unsigned boff = stg ? BS_STRIDE : 0u;
        #pragma unroll
        for(int s=0;s<2;s++){
            unsigned af[2][4], bf[4];
            ldsm4 (af[0], aaddr[0][s] + aoff);
            ldsm4 (af[1], aaddr[1][s] + aoff);
            ldsm4t(bf,    baddr[s]    + boff);
            #pragma unroll
            for(int mi=0;mi<2;mi++)
                #pragma unroll
                for(int ni=0;ni<2;ni++)
                    mma16816(acc[mi][ni], af[mi], bf[ni*2], bf[ni*2+1]);
        }
        if(it+1 < NIT){
            int nstg = stg^1;
            *reinterpret_cast<uint4*>(&As[nstg][arow][acol]) = ar;
            *reinterpret_cast<uint4*>(&Bs[nstg][brow][bcol]) = br;
            __syncthreads();
            stg = nstg;
        }
    }

    // epilogue
    #pragma unroll
    for(int mi=0;mi<2;mi++){
        #pragma unroll
        for(int ni=0;ni<2;ni++){
            int c0 = n0 + wn + ni*8 + (lane&3)*2;
            if(c0 >= 600) continue;
            #pragma unroll
            for(int hf=0; hf<2; hf++){
                int r = m0 + wm + mi*16 + (lane>>2) + hf*8;
                float v0 = acc[mi][ni][hf*2], v1 = acc[mi][ni][hf*2+1];
                if(EPI==0){
                    *reinterpret_cast<__half2*>(x1out + (size_t)r*H + c0)
                        = __floats2half2_rn(v0, v1);
                } else {
                    v0 += bias[c0]; v1 += bias[c0+1];
                    if(EPI==1){
                        v0 = sspf(v0); v1 = sspf(v1);
                    } else {
                        float2 hv = *reinterpret_cast<float2*>(hbuf + (size_t)r*H + c0);
                        v0 += hv.x; v1 += hv.y;
                        *reinterpret_cast<float2*>(hbuf + (size_t)r*H + c0) = make_float2(v0, v1);
                    }
                    split_store(sout, (size_t)r*K2 + c0, v0, v1);
                }
            }
        }
    }
}

// ---- batched SIMT fp32 GEMM for table build (small, exact) ----
// EPI: 1 ssp, 3 *=extra[m]
template<int EPI>
__global__ void __launch_bounds__(256) sgemm_b(const float* A, const float* B,
        const float* bias, const float* extra, float* Cm,
        int M, int N, int K, long sA, long sB, long sb, long sC){
    int zb = blockIdx.z;
    A  += (size_t)zb * sA;
    B  += (size_t)zb * sB;
    Cm += (size_t)zb * sC;
    if(bias) bias += (size_t)zb * sb;

    const int BM=64, BN=64, BK=16;
    __shared__ float As[BK][BM], Bs[BK][BN];
    int tid=threadIdx.x, tx=tid&15, ty=tid>>4;
    int m0=blockIdx.y*BM, n0=blockIdx.x*BN;
    int ar=tid>>2, ac=(tid&3)<<2, br=tid>>4, bc=(tid&15)<<2;
    float acc[4][4];
    #pragma unroll
    for(int a=0;a<4;a++)
        #pragma unroll
        for(int c=0;c<4;c++) acc[a][c]=0.f;
    for(int k0=0;k0<K;k0+=BK){
        int gm=m0+ar;
        #pragma unroll
        for(int u=0;u<4;u++){
            int gk=k0+ac+u;
            As[ac+u][ar] = (gm<M && gk<K) ? A[(size_t)gm*K+gk] : 0.f;
        }
        int gk2=k0+br;
        #pragma unroll
        for(int u=0;u<4;u++){
            int gn=n0+bc+u;
            Bs[br][bc+u] = (gk2<K && gn<N) ? B[(size_t)gk2*N+gn] : 0.f;
        }
        __syncthreads();
        #pragma unroll
        for(int kk=0;kk<BK;kk++){
            float4 av=*reinterpret_cast<const float4*>(&As[kk][ty<<2]);
            float4 bv=*reinterpret_cast<const float4*>(&Bs[kk][tx<<2]);
            float a0=av.x,a1=av.y,a2=av.z,a3=av.w;
            float b0=bv.x,b1=bv.y,b2=bv.z,b3=bv.w;
            acc[0][0]=fmaf(a0,b0,acc[0][0]); acc[0][1]=fmaf(a0,b1,acc[0][1]);
            acc[0][2]=fmaf(a0,b2,acc[0][2]); acc[0][3]=fmaf(a0,b3,acc[0][3]);
            acc[1][0]=fmaf(a1,b0,acc[1][0]); acc[1][1]=fmaf(a1,b1,acc[1][1]);
            acc[1][2]=fmaf(a1,b2,acc[1][2]); acc[1][3]=fmaf(a1,b3,acc[1][3]);
            acc[2][0]=fmaf(a2,b0,acc[2][0]); acc[2][1]=fmaf(a2,b1,acc[2][1]);
            acc[2][2]=fmaf(a2,b2,acc[2][2]); acc[2][3]=fmaf(a2,b3,acc[2][3]);
            acc[3][0]=fmaf(a3,b0,acc[3][0]); acc[3][1]=fmaf(a3,b1,acc[3][1]);
            acc[3][2]=fmaf(a3,b2,acc[3][2]); acc[3][3]=fmaf(a3,b3,acc[3][3]);
        }
        __syncthreads();
    }
    #pragma unroll
    for(int ii=0;ii<4;ii++){
        int m=m0+(ty<<2)+ii;
        if(m>=M) continue;
        #pragma unroll
        for(int jj=0;jj<4;jj++){
            int n=n0+(tx<<2)+jj;
            if(n>=N) continue;
            float v=acc[ii][jj];
            if(bias) v += bias[n];
            if(EPI==1) v = sspf(v);
            else if(EPI==3) v *= extra[m];
            Cm[(size_t)m*N+n]=v;
        }
    }
}

__global__ void pool(){
    int idx = blockIdx.x*blockDim.x + threadIdx.x;
    if(idx >= NB*H) return;
    int b = idx/H, h = idx - b*H;
    const float* p = g_h + (size_t)b*NPG*H + h;
    float s = 0.f;
    #pragma unroll 8
    for(int n=0;n<NPG;n++) s += p[(size_t)n*H];
    g_pool[idx] = s * (1.0f/NPG);
}

__global__ void final_lin(const float* __restrict__ pw, const float* __restrict__ pb,
                          float* __restrict__ out){
    int idx = blockIdx.x*blockDim.x + threadIdx.x;
    if(idx >= NB*H) return;
    int b = idx/H, n = idx - b*H;
    const float* pr = g_pool + b*H;
    float s = pb[n];
    for(int k=0;k<H;k++) s = fmaf(pr[k], pw[(size_t)k*H+n], s);
    out[idx] = s;
}

extern "C" void kernel_launch(void* const* d_in, const int* in_sizes, int n_in,
                              void* d_out, int out_size){
    // dict order: z,pos,emb,w1,b1,w2,b2,lin1,l2w,l2b,ilw,ilb,pw,pb
    int map[14] = {0,1,2,3,4,5,6,7,8,9,10,11,12,13};
    if(!(in_sizes[0]==1024 && in_sizes[1]==3072)){
        int sig[14] = {13,0,1,2,3,4,5,6,7,8,9,10,11,12};
        for(int i=0;i<14;i++) map[i]=sig[i];
    }
    const int*   z    = (const int*)  d_in[map[0]];
    const float* posv = (const float*)d_in[map[1]];
    const float* emb  = (const float*)d_in[map[2]];
    const float* w1   = (const float*)d_in[map[3]];
    const float* b1   = (const float*)d_in[map[4]];
    const float* w2   = (const float*)d_in[map[5]];
    const float* b2   = (const float*)d_in[map[6]];
    const float* lin1 = (const float*)d_in[map[7]];
    const float* l2w  = (const float*)d_in[map[8]];
    const float* l2b  = (const float*)d_in[map[9]];
    const float* ilw  = (const float*)d_in[map[10]];
    const float* ilb  = (const float*)d_in[map[11]];
    const float* pw   = (const float*)d_in[map[12]];
    const float* pb   = (const float*)d_in[map[13]];
    float* out = (float*)d_out;

    float *p_h,*p_T,*p_tmp,*p_ea,*p_C;
    __nv_bfloat16 *p_As0,*p_As1,*p_As2,*p_Bw;
    __half *p_x1h;
    cudaGetSymbolAddress((void**)&p_h,   g_h);
    cudaGetSymbolAddress((void**)&p_T,   g_T);
    cudaGetSymbolAddress((void**)&p_tmp, g_tmp);
    cudaGetSymbolAddress((void**)&p_ea,  g_ea);
    cudaGetSymbolAddress((void**)&p_C,   g_C);
    cudaGetSymbolAddress((void**)&p_As0, g_As0);
    cudaGetSymbolAddress((void**)&p_As1, g_As1);
    cudaGetSymbolAddress((void**)&p_As2, g_As2);
    cudaGetSymbolAddress((void**)&p_Bw,  g_Bw);
    cudaGetSymbolAddress((void**)&p_x1h, g_x1h);

    build_graph<<<NN, NPG>>>(posv);
    smear<<<(NC*G+255)/256, 256>>>();
    embed<<<(NN*H+255)/256, 256>>>(emb, z);
    wsplit<<<(18*H*H+255)/256, 256>>>(lin1, l2w, ilw);

    // coarse filter tables (exact fp32) then fine fp16 upsample
    dim3 gT((H+63)/64, (NC+63)/64, NL);
    sgemm_b<1><<<gT,256>>>(p_ea, w1, b1, nullptr, p_tmp,
                           NC, H, G, 0L, (long)G*H, (long)H, (long)NC*H);
    sgemm_b<3><<<gT,256>>>(p_tmp, w2, b2, p_C, p_T,
                           NC, H, H, (long)NC*H, (long)H*H, (long)H, (long)NC*H);
    dim3 gU((PFP1*H+255)/256, NL);
    upsample<<<gU, 256>>>();

    dim3 gG(10, 16);   // n-tiles (64) x m-tiles (64) = 160 blocks
    for(int l=0;l<NL;l++){
        const __nv_bfloat16* Blin1 = p_Bw + (size_t)(l*3+0)*K2*H;
        const __nv_bfloat16* Bl2w  = p_Bw + (size_t)(l*3+1)*K2*H;
        const __nv_bfloat16* Bilw  = p_Bw + (size_t)(l*3+2)*K2*H;
        // x1 = h @ lin1 -> fp16
        bgemm<0><<<gG,256>>>(p_As0, Blin1, nullptr, nullptr, nullptr, p_x1h);
        // msg (split) from neighbor aggregation
        agg<<<NN, 320>>>(l);
        // m1 = ssp(msg @ l2w + l2b) -> split
        bgemm<1><<<gG,256>>>(p_As1, Bl2w, l2b+(size_t)l*H, nullptr, p_As2, nullptr);
        // h = h + (m1 @ ilw + ilb); emits h split for next layer
        bgemm<2><<<gG,256>>>(p_As2, Bilw, ilb+(size_t)l*H, p_h, p_As0, nullptr);
    }
    pool<<<(NB*H+255)/256, 256>>>();
    final_lin<<<(NB*H+255)/256, 256>>>(pw, pb, out);
}

// round 10
// speedup vs baseline: 1.5072x; 1.2419x over previous
#include <cuda_runtime.h>
#include <cuda_fp16.h>
#include <cuda_bf16.h>
#include <math.h>

#define NN 1024
#define NPG 128
#define NB 8
#define KM 64
#define H 600
#define G 50
#define NL 6
#define NC 259           // coarse knots, d=(q-1)*D0, q=0..258
#define D0 (10.0f/256.0f)
#define K2 1824          // split-K' = 3*600 padded to multiple of 32
#define NIT 57           // K2/32
#define MT 320           // padded M for table gemm (5 tiles of 64)

// ---------------- device scratch (zero-initialized at module load) ----------------
__device__ __align__(16) float g_h[NN*H];
__device__ __align__(16) __half g_x1h[NN*H];
__device__ __align__(16) __nv_bfloat16 g_As0[(size_t)NN*K2];   // h split
__device__ __align__(16) __nv_bfloat16 g_As1[(size_t)NN*K2];   // msg split
__device__ __align__(16) __nv_bfloat16 g_As2[(size_t)NN*K2];   // m1 split
__device__ __align__(16) __nv_bfloat16 g_Ast[(size_t)NL*MT*K2]; // tmp split (table)
__device__ __align__(16) __nv_bfloat16 g_Bw[(size_t)18*K2*H + 1024];  // lin1,l2w,ilw splits
__device__ __align__(16) __nv_bfloat16 g_Bw2[(size_t)NL*K2*H + 1024]; // w2 splits
__device__ __align__(16) float g_tmp[NL*NC*H], g_ea[NC*G], g_C[NC];
__device__ __align__(16) __half g_Th[NL*NC*H];   // coarse fp16 filter tables
__device__ float g_pool[NB*H];
__device__ int   g_nbr[NN*KM], g_base[NN*KM], g_cnt[NN];
__device__ __align__(16) float g_w4[NN*KM*4];

__device__ __forceinline__ float sspf(float x){
    float r = (x > 0.f) ? (x + log1pf(expf(-x))) : log1pf(expf(x));
    return r - 0.69314718055994530942f;
}

__device__ __forceinline__ void split_store(__nv_bfloat16* base, size_t off,
                                            float v0, float v1){
    __nv_bfloat16 h0=__float2bfloat16(v0), h1=__float2bfloat16(v1);
    __nv_bfloat162 hi2; hi2.x=h0; hi2.y=h1;
    __nv_bfloat162 lo2;
    lo2.x=__float2bfloat16(v0-__bfloat162float(h0));
    lo2.y=__float2bfloat16(v1-__bfloat162float(h1));
    __nv_bfloat162* dp = reinterpret_cast<__nv_bfloat162*>(base + off);
    dp[0]   = hi2;     // k = c       (A_hi)
    dp[300] = hi2;     // k = 600+c   (A_hi)
    dp[600] = lo2;     // k = 1200+c  (A_lo)
}

// ---- graph build: 1 block per node, matches jax top_k(-dist2, K); cubic weights ----
__global__ void build_graph(const float* __restrict__ pos){
    int i = blockIdx.x, b = i/NPG, il = i - b*NPG, j = threadIdx.x;
    __shared__ float sx[NPG], sy[NPG], sz[NPG], sd2[NPG];
    __shared__ int scnt;
    const float* pg = pos + (size_t)b*NPG*3;
    sx[j]=pg[j*3]; sy[j]=pg[j*3+1]; sz[j]=pg[j*3+2];
    if(j==0) scnt=0;
    __syncthreads();
    float dx=__fsub_rn(sx[il],sx[j]), dy=__fsub_rn(sy[il],sy[j]), dz=__fsub_rn(sz[il],sz[j]);
    float d2=__fadd_rn(__fadd_rn(__fmul_rn(dx,dx),__fmul_rn(dy,dy)),__fmul_rn(dz,dz));
    bool ok = (d2<=100.0f) && (j!=il);
    sd2[j] = ok ? d2 : 3.0e38f;
    __syncthreads();
    int rank=0;
    if(ok){
        #pragma unroll 8
        for(int t=0;t<NPG;t++){ float o=sd2[t]; rank += (o<d2)||(o==d2 && t<j); }
        atomicAdd(&scnt,1);
    }
    __syncthreads();
    if(j==0) g_cnt[i] = min(scnt,KM);
    if(ok && rank<KM){
        float d = sqrtf(d2);
        float u = d * (1.0f/D0);
        int s = (int)u; if(s>255) s=255; if(s<0) s=0;
        float t = u - (float)s;
        float t2=t*t, t3=t2*t;
        int e=i*KM+rank;
        g_nbr[e]=b*NPG+j; g_base[e]=s*H;
        g_w4[e*4+0]=0.5f*(-t3+2.f*t2-t);
        g_w4[e*4+1]=0.5f*(3.f*t3-5.f*t2+2.f);
        g_w4[e*4+2]=0.5f*(-3.f*t3+4.f*t2+t);
        g_w4[e*4+3]=0.5f*(t3-t2);
    }
}

// ---- gaussian smearing + cosine cutoff on coarse grid ----
__global__ void smear(){
    int idx = blockIdx.x*blockDim.x + threadIdx.x;
    if(idx >= NC*G) return;
    int q = idx/G, g = idx - q*G;
    float d = (float)(q-1)*D0;
    float step = 10.0f/49.0f;
    float x = d - (float)g*step;
    g_ea[idx] = expf((-0.5f/(step*step))*x*x);
    if(g==0) g_C[q] = 0.5f*(cosf(d*0.31415926535897932f)+1.0f);
}

// ---- embedding gather + h split ----
__global__ void embed(const float* __restrict__ emb, const int* __restrict__ z){
    int idx = blockIdx.x*blockDim.x + threadIdx.x;
    if(idx >= NN*H) return;
    int i = idx/H, c = idx - i*H;
    float v = emb[z[i]*H + c];
    g_h[idx] = v;
    __nv_bfloat16 hi = __float2bfloat16(v);
    g_As0[(size_t)i*K2 + c]        = hi;
    g_As0[(size_t)i*K2 + 600 + c]  = hi;
    g_As0[(size_t)i*K2 + 1200 + c] = __float2bfloat16(v - __bfloat162float(hi));
}

// ---- weight split: 24 [600,600] fp32 -> bf16 hi/lo/hi rows ----
__global__ void wsplit(const float* __restrict__ lin1, const float* __restrict__ l2w,
                       const float* __restrict__ ilw, const float* __restrict__ w2){
    int idx = blockIdx.x*blockDim.x + threadIdx.x;
    if(idx >= 24*H*H) return;
    int w = idx/(H*H), e = idx - w*(H*H), r = e/H, c = e - r*H;
    int l = w>>2, kind = w&3;
    const float* src = (kind==0) ? lin1 : (kind==1) ? l2w : (kind==2) ? ilw : w2;
    float v = src[(size_t)l*H*H + e];
    __nv_bfloat16 hi = __float2bfloat16(v);
    __nv_bfloat16* dst = (kind<3) ? (g_Bw + (size_t)(l*3+kind)*K2*H)
                                  : (g_Bw2 + (size_t)l*K2*H);
    dst[(size_t)r*H + c]          = hi;
    dst[(size_t)(600+r)*H + c]    = __float2bfloat16(v - __bfloat162float(hi));
    dst[(size_t)(1200+r)*H + c]   = hi;
}

// ---- split of table stage-1 output (tmp) into A' layout ----
__global__ void split_tmp(){
    int idx = blockIdx.x*blockDim.x + threadIdx.x;
    if(idx >= NL*NC*H) return;
    int l = idx/(NC*H), rem = idx - l*(NC*H), q = rem/H, c = rem - q*H;
    float v = g_tmp[idx];
    __nv_bfloat16 hi = __float2bfloat16(v);
    __nv_bfloat16* row = g_Ast + (size_t)(l*MT + q)*K2;
    row[c]        = hi;
    row[600 + c]  = hi;
    row[1200 + c] = __float2bfloat16(v - __bfloat162float(hi));
}

// ---- aggregation: cubic interp of fp16 coarse table * fp16 x1; emits msg split ----
__global__ void __launch_bounds__(320) agg(int l){
    int i = blockIdx.x, t = threadIdx.x;
    __shared__ int s_j[KM], s_b[KM], s_cnt;
    __shared__ float4 s_w[KM];
    if(t==0) s_cnt = g_cnt[i];
    if(t<KM){
        int e=i*KM+t;
        s_j[t]=g_nbr[e]*H; s_b[t]=g_base[e];
        s_w[t]=*reinterpret_cast<const float4*>(&g_w4[e*4]);
    }
    __syncthreads();
    if(t >= 300) return;
    int h = t*2;
    const __half* T = g_Th + (size_t)l*NC*H;
    int cnt = s_cnt;
    float ax = 0.f, ay = 0.f;
    #pragma unroll 2
    for(int k=0;k<cnt;k++){
        const __half2* tp = reinterpret_cast<const __half2*>(T + s_b[k] + h);
        float2 t0=__half22float2(__ldg(tp));
        float2 t1=__half22float2(__ldg(tp+300));
        float2 t2=__half22float2(__ldg(tp+600));
        float2 t3=__half22float2(__ldg(tp+900));
        float2 x2=__half22float2(__ldg(reinterpret_cast<const __half2*>(&g_x1h[s_j[k]+h])));
        float4 w = s_w[k];
        float vx = w.x*t0.x + w.y*t1.x + w.z*t2.x + w.w*t3.x;
        float vy = w.x*t0.y + w.y*t1.y + w.z*t2.y + w.w*t3.y;
        ax = fmaf(vx, x2.x, ax);
        ay = fmaf(vy, x2.y, ay);
    }
    split_store(g_As1, (size_t)i*K2 + h, ax, ay);
}

// ---- mma / cp.async helpers ----
__device__ __forceinline__ void ldsm4(unsigned* r, unsigned addr){
    asm volatile("ldmatrix.sync.aligned.m8n8.x4.shared.b16 {%0,%1,%2,%3}, [%4];"
        : "=r"(r[0]),"=r"(r[1]),"=r"(r[2]),"=r"(r[3]) : "r"(addr));
}
__device__ __forceinline__ void ldsm4t(unsigned* r, unsigned addr){
    asm volatile("ldmatrix.sync.aligned.m8n8.x4.trans.shared.b16 {%0,%1,%2,%3}, [%4];"
        : "=r"(r[0]),"=r"(r[1]),"=r"(r[2]),"=r"(r[3]) : "r"(addr));
}
__device__ __forceinline__ void mma16816(float* c, const unsigned* a, unsigned b0, unsigned b1){
    asm volatile("mma.sync.aligned.m16n8k16.row.col.f32.bf16.bf16.f32 "
        "{%0,%1,%2,%3}, {%4,%5,%6,%7}, {%8,%9}, {%0,%1,%2,%3};"
        : "+f"(c[0]),"+f"(c[1]),"+f"(c[2]),"+f"(c[3])
        : "r"(a[0]),"r"(a[1]),"r"(a[2]),"r"(a[3]), "r"(b0),"r"(b1));
}
#define CPA16(dst,src) asm volatile("cp.async.cg.shared.global [%0], [%1], 16;\n"::"r"(dst),"l"(src))
#define CPC()  asm volatile("cp.async.commit_group;\n")
#define CPW2() asm volatile("cp.async.wait_group 2;\n" ::: "memory")
#define CPW0() asm volatile("cp.async.wait_group 0;\n" ::: "memory")

#define ASTG (64*40*2)
#define BSTG (32*72*2)

// ================= shared mainloop macro body via device inline =================
// 256 threads, 8 warps (2m x 4n), 64x64 CTA tile, K2=1824, 4-stage cp.async.
struct Frag { unsigned aF[2][2]; unsigned bF[2]; unsigned aD, bD; };

__device__ __forceinline__ void gemm_mainloop(
        const __nv_bfloat16* aptr, const __nv_bfloat16* bptr,
        __nv_bfloat16 (*As)[64][40], __nv_bfloat16 (*Bs)[32][72],
        const Frag& f, float acc[2][2][4]){
    // prologue: stages 0,1
    CPA16(f.aD, aptr); CPA16(f.bD, bptr); CPC();
    CPA16(f.aD+ASTG, aptr+32); CPA16(f.bD+BSTG, bptr+(size_t)32*H); CPC();
    for(int it=0; it<NIT; it++){
        int pre = it+2;
        if(pre < NIT){
            int sb = pre & 3;
            CPA16(f.aD + sb*ASTG, aptr + pre*32);
            CPA16(f.bD + sb*BSTG, bptr + (size_t)(pre*32)*H);
        }
        CPC();
        if(it < NIT-2) CPW2(); else CPW0();
        __syncthreads();
        unsigned ao = (it&3)*ASTG, bo = (it&3)*BSTG;
        #pragma unroll
        for(int s=0;s<2;s++){
            unsigned af[2][4], bf[4];
            ldsm4 (af[0], f.aF[0][s] + ao);
            ldsm4 (af[1], f.aF[1][s] + ao);
            ldsm4t(bf,    f.bF[s]    + bo);
            mma16816(acc[0][0], af[0], bf[0], bf[1]);
            mma16816(acc[0][1], af[0], bf[2], bf[3]);
            mma16816(acc[1][0], af[1], bf[0], bf[1]);
            mma16816(acc[1][1], af[1], bf[2], bf[3]);
        }
    }
}

__device__ __forceinline__ Frag make_frag(
        __nv_bfloat16 (*As)[64][40], __nv_bfloat16 (*Bs)[32][72],
        int tid, int wm, int wn, int lane, int arow, int acol, int brow, int bcol){
    Frag f;
    f.aD = (unsigned)__cvta_generic_to_shared(&As[0][arow][acol]);
    f.bD = (unsigned)__cvta_generic_to_shared(&Bs[0][brow][bcol]);
    #pragma unroll
    for(int mi=0;mi<2;mi++)
        #pragma unroll
        for(int s=0;s<2;s++)
            f.aF[mi][s] = (unsigned)__cvta_generic_to_shared(
                &As[0][wm + mi*16 + (lane&15)][s*16 + (lane>>4)*8]);
    #pragma unroll
    for(int s=0;s<2;s++)
        f.bF[s] = (unsigned)__cvta_generic_to_shared(
            &Bs[0][s*16 + (lane&15)][wn + (lane>>4)*8]);
    return f;
}

// ---- node GEMM: C[1024,600] = A'[1024,1824] @ B'[1824,600], fused epilogue ----
// EPI 0: -> x1h fp16. EPI 1: ssp(+bias) -> split sout. EPI 2: +bias+h residual -> h & split sout.
template<int EPI>
__global__ void __launch_bounds__(256) bgemm(const __nv_bfloat16* __restrict__ Ap,
        const __nv_bfloat16* __restrict__ Bp, const float* __restrict__ bias,
        float* __restrict__ hbuf, __nv_bfloat16* __restrict__ sout,
        __half* __restrict__ x1out){
    __shared__ __nv_bfloat16 As[4][64][40];
    __shared__ __nv_bfloat16 Bs[4][32][72];
    int tid=threadIdx.x, warp=tid>>5, lane=tid&31;
    int m0=blockIdx.y*64, n0=blockIdx.x*64;
    int wm=(warp>>2)*32, wn=(warp&3)*16;
    int arow=tid>>2, acol=(tid&3)*8;
    int brow=tid>>3, bcol=(tid&7)*8;
    Frag f = make_frag(As, Bs, tid, wm, wn, lane, arow, acol, brow, bcol);
    float acc[2][2][4];
    #pragma unroll
    for(int mi=0;mi<2;mi++)
        #pragma unroll
        for(int ni=0;ni<2;ni++)
            #pragma unroll
            for(int q=0;q<4;q++) acc[mi][ni][q]=0.f;
    const __nv_bfloat16* aptr = Ap + (size_t)(m0+arow)*K2 + acol;
    const __nv_bfloat16* bptr = Bp + (size_t)brow*H + n0 + bcol;
    gemm_mainloop(aptr, bptr, As, Bs, f, acc);

    #pragma unroll
    for(int mi=0;mi<2;mi++){
        #pragma unroll
        for(int ni=0;ni<2;ni++){
            int c0 = n0 + wn + ni*8 + (lane&3)*2;
            if(c0 >= 600) continue;
            #pragma unroll
            for(int hf=0; hf<2; hf++){
                int r = m0 + wm + mi*16 + (lane>>2) + hf*8;
                float v0 = acc[mi][ni][hf*2], v1 = acc[mi][ni][hf*2+1];
                if(EPI==0){
                    *reinterpret_cast<__half2*>(x1out + (size_t)r*H + c0)
                        = __floats2half2_rn(v0, v1);
                } else {
                    v0 += bias[c0]; v1 += bias[c0+1];
                    if(EPI==1){
                        v0 = sspf(v0); v1 = sspf(v1);
                    } else {
                        float2 hv = *reinterpret_cast<float2*>(hbuf + (size_t)r*H + c0);
                        v0 += hv.x; v1 += hv.y;
                        *reinterpret_cast<float2*>(hbuf + (size_t)r*H + c0) = make_float2(v0, v1);
                    }
                    split_store(sout, (size_t)r*K2 + c0, v0, v1);
                }
            }
        }
    }
}

// ---- table GEMM: for each layer, T = (tmp' @ w2' + b2) * C, write fp16 table ----
__global__ void __launch_bounds__(256) tbgemm(const float* __restrict__ b2){
    __shared__ __nv_bfloat16 As[4][64][40];
    __shared__ __nv_bfloat16 Bs[4][32][72];
    int zb = blockIdx.z;
    int tid=threadIdx.x, warp=tid>>5, lane=tid&31;
    int m0=blockIdx.y*64, n0=blockIdx.x*64;
    int wm=(warp>>2)*32, wn=(warp&3)*16;
    int arow=tid>>2, acol=(tid&3)*8;
    int brow=tid>>3, bcol=(tid&7)*8;
    Frag f = make_frag(As, Bs, tid, wm, wn, lane, arow, acol, brow, bcol);
    float acc[2][2][4];
    #pragma unroll
    for(int mi=0;mi<2;mi++)
        #pragma unroll
        for(int ni=0;ni<2;ni++)
            #pragma unroll
            for(int q=0;q<4;q++) acc[mi][ni][q]=0.f;
    const __nv_bfloat16* aptr = g_Ast + (size_t)zb*MT*K2 + (size_t)(m0+arow)*K2 + acol;
    const __nv_bfloat16* bptr = g_Bw2 + (size_t)zb*K2*H + (size_t)brow*H + n0 + bcol;
    gemm_mainloop(aptr, bptr, As, Bs, f, acc);

    const float* bias = b2 + (size_t)zb*H;
    #pragma unroll
    for(int mi=0;mi<2;mi++){
        #pragma unroll
        for(int ni=0;ni<2;ni++){
            int c0 = n0 + wn + ni*8 + (lane&3)*2;
            if(c0 >= 600) continue;
            #pragma unroll
            for(int hf=0; hf<2; hf++){
                int r = m0 + wm + mi*16 + (lane>>2) + hf*8;
                if(r >= NC) continue;
                float cc = g_C[r];
                float v0 = (acc[mi][ni][hf*2]   + bias[c0])   * cc;
                float v1 = (acc[mi][ni][hf*2+1] + bias[c0+1]) * cc;
                *reinterpret_cast<__half2*>(g_Th + (size_t)zb*NC*H + (size_t)r*H + c0)
                    = __floats2half2_rn(v0, v1);
            }
        }
    }
}

// ---- small batched SIMT fp32 GEMM for table stage-1 (K=50), EPI=ssp ----
__global__ void __launch_bounds__(256) sgemm1(const float* __restrict__ w1,
        const float* __restrict__ b1){
    int zb = blockIdx.z;
    const float* A = g_ea;
    const float* B = w1 + (size_t)zb*G*H;
    const float* bias = b1 + (size_t)zb*H;
    float* Cm = g_tmp + (size_t)zb*NC*H;
    const int BM=64, BN=64, BK=10;
    __shared__ float As[BK][BM], Bs[BK][BN];
    int tid=threadIdx.x, tx=tid&15, ty=tid>>4;
    int m0=blockIdx.y*BM, n0=blockIdx.x*BN;
    int ar=tid&63, ac=tid>>6;          // A: 64 rows x (4 k per pass)
    int br=tid>>6, bc=(tid&63);        // B: 4 k-rows x 64 cols per pass
    float acc[4][4];
    #pragma unroll
    for(int a=0;a<4;a++)
        #pragma unroll
        for(int c=0;c<4;c++) acc[a][c]=0.f;
    for(int k0=0;k0<G;k0+=BK){
        #pragma unroll
        for(int u=0;u<3;u++){
            int kk = ac + u*4;
            if(kk<BK){
                int gm=m0+ar, gk=k0+kk;
                As[kk][ar] = (gm<NC && gk<G) ? A[(size_t)gm*G+gk] : 0.f;
            }
        }
        #pragma unroll
        for(int u=0;u<3;u++){
            int kk = br + u*4;
            if(kk<BK){
                int gk=k0+kk, gn=n0+bc;
                Bs[kk][bc] = (gk<G && gn<H) ? B[(size_t)gk*H+gn] : 0.f;
            }
        }
        __syncthreads();
        #pragma unroll
        for(int kk=0;kk<BK;kk++){
            float4 av=*reinterpret_cast<const float4*>(&As[kk][ty<<2]);
            float4 bv=*reinterpret_cast<const float4*>(&Bs[kk][tx<<2]);
            float a0=av.x,a1=av.y,a2=av.z,a3=av.w;
            float b0=bv.x,b1=bv.y,b2=bv.z,b3=bv.w;
            acc[0][0]=fmaf(a0,b0,acc[0][0]); acc[0][1]=fmaf(a0,b1,acc[0][1]);
            acc[0][2]=fmaf(a0,b2,acc[0][2]); acc[0][3]=fmaf(a0,b3,acc[0][3]);
            acc[1][0]=fmaf(a1,b0,acc[1][0]); acc[1][1]=fmaf(a1,b1,acc[1][1]);
            acc[1][2]=fmaf(a1,b2,acc[1][2]); acc[1][3]=fmaf(a1,b3,acc[1][3]);
            acc[2][0]=fmaf(a2,b0,acc[2][0]); acc[2][1]=fmaf(a2,b1,acc[2][1]);
            acc[2][2]=fmaf(a2,b2,acc[2][2]); acc[2][3]=fmaf(a2,b3,acc[2][3]);
            acc[3][0]=fmaf(a3,b0,acc[3][0]); acc[3][1]=fmaf(a3,b1,acc[3][1]);
            acc[3][2]=fmaf(a3,b2,acc[3][2]); acc[3][3]=fmaf(a3,b3,acc[3][3]);
        }
        __syncthreads();
    }
    #pragma unroll
    for(int ii=0;ii<4;ii++){
        int m=m0+(ty<<2)+ii;
        if(m>=NC) continue;
        #pragma unroll
        for(int jj=0;jj<4;jj++){
            int n=n0+(tx<<2)+jj;
            if(n>=H) continue;
            Cm[(size_t)m*H+n] = sspf(acc[ii][jj] + bias[n]);
        }
    }
}

__global__ void pool(){
    int idx = blockIdx.x*blockDim.x + threadIdx.x;
    if(idx >= NB*H) return;
    int b = idx/H, h = idx - b*H;
    const float* p = g_h + (size_t)b*NPG*H + h;
    float s = 0.f;
    #pragma unroll 8
    for(int n=0;n<NPG;n++) s += p[(size_t)n*H];
    g_pool[idx] = s * (1.0f/NPG);
}

__global__ void final_lin(const float* __restrict__ pw, const float* __restrict__ pb,
                          float* __restrict__ out){
    int idx = blockIdx.x*blockDim.x + threadIdx.x;
    if(idx >= NB*H) return;
    int b = idx/H, n = idx - b*H;
    const float* pr = g_pool + b*H;
    float s = pb[n];
    for(int k=0;k<H;k++) s = fmaf(pr[k], pw[(size_t)k*H+n], s);
    out[idx] = s;
}

extern "C" void kernel_launch(void* const* d_in, const int* in_sizes, int n_in,
                              void* d_out, int out_size){
    // dict order: z,pos,emb,w1,b1,w2,b2,lin1,l2w,l2b,ilw,ilb,pw,pb
    int map[14] = {0,1,2,3,4,5,6,7,8,9,10,11,12,13};
    if(!(in_sizes[0]==1024 && in_sizes[1]==3072)){
        int sig[14] = {13,0,1,2,3,4,5,6,7,8,9,10,11,12};
        for(int i=0;i<14;i++) map[i]=sig[i];
    }
    const int*   z    = (const int*)  d_in[map[0]];
    const float* posv = (const float*)d_in[map[1]];
    const float* emb  = (const float*)d_in[map[2]];
    const float* w1   = (const float*)d_in[map[3]];
    const float* b1   = (const float*)d_in[map[4]];
    const float* w2   = (const float*)d_in[map[5]];
    const float* b2   = (const float*)d_in[map[6]];
    const float* lin1 = (const float*)d_in[map[7]];
    const float* l2w  = (const float*)d_in[map[8]];
    const float* l2b  = (const float*)d_in[map[9]];
    const float* ilw  = (const float*)d_in[map[10]];
    const float* ilb  = (const float*)d_in[map[11]];
    const float* pw   = (const float*)d_in[map[12]];
    const float* pb   = (const float*)d_in[map[13]];
    float* out = (float*)d_out;

    float *p_h;
    __nv_bfloat16 *p_As0,*p_As1,*p_As2,*p_Bw;
    __half *p_x1h;
    cudaGetSymbolAddress((void**)&p_h,   g_h);
    cudaGetSymbolAddress((void**)&p_As0, g_As0);
    cudaGetSymbolAddress((void**)&p_As1, g_As1);
    cudaGetSymbolAddress((void**)&p_As2, g_As2);
    cudaGetSymbolAddress((void**)&p_Bw,  g_Bw);
    cudaGetSymbolAddress((void**)&p_x1h, g_x1h);

    build_graph<<<NN, NPG>>>(posv);
    smear<<<(NC*G+255)/256, 256>>>();
    embed<<<(NN*H+255)/256, 256>>>(emb, z);
    wsplit<<<(24*H*H+255)/256, 256>>>(lin1, l2w, ilw, w2);

    // table: stage-1 FFMA (K=50) -> split -> tensor-core stage-2 with fused C/bias/half
    dim3 gT1((H+63)/64, (NC+63)/64, NL);
    sgemm1<<<gT1, 256>>>(w1, b1);
    split_tmp<<<(NL*NC*H+255)/256, 256>>>();
    dim3 gTB((H+63)/64, MT/64, NL);   // 10 x 5 x 6
    tbgemm<<<gTB, 256>>>(b2);

    dim3 gG(10, 16);   // 160 blocks
    for(int l=0;l<NL;l++){
        const __nv_bfloat16* Blin1 = p_Bw + (size_t)(l*3+0)*K2*H;
        const __nv_bfloat16* Bl2w  = p_Bw + (size_t)(l*3+1)*K2*H;
        const __nv_bfloat16* Bilw  = p_Bw + (size_t)(l*3+2)*K2*H;
        bgemm<0><<<gG,256>>>(p_As0, Blin1, nullptr, nullptr, nullptr, p_x1h);
        agg<<<NN, 320>>>(l);
        bgemm<1><<<gG,256>>>(p_As1, Bl2w, l2b+(size_t)l*H, nullptr, p_As2, nullptr);
        bgemm<2><<<gG,256>>>(p_As2, Bilw, ilb+(size_t)l*H, p_h, p_As0, nullptr);
    }
    pool<<<(NB*H+255)/256, 256>>>();
    final_lin<<<(NB*H+255)/256, 256>>>(pw, pb, out);
}

// round 11
// speedup vs baseline: 1.5755x; 1.0453x over previous
#include <cuda_runtime.h>
#include <cuda_fp16.h>
#include <cuda_bf16.h>
#include <math.h>

#define NN 1024
#define NPG 128
#define NB 8
#define KM 64
#define H 600
#define G 50
#define NL 6
#define NC 259           // coarse knots, d=(q-1)*D0, q=0..258
#define D0 (10.0f/256.0f)
#define K2 1824          // A' width: [hi(608) | hi(608) | lo(608)]
#define KB2 1216         // B' rows:  [hi(608) ; lo(608)]  (third block remapped)
#define NIT 57           // K2/32
#define MT 320           // padded M for table gemm (10 tiles of 32)

// ---------------- device scratch (zero-initialized at module load) ----------------
__device__ __align__(16) float g_h[NN*H];
__device__ __align__(16) __half g_x1h[NN*H];
__device__ __align__(16) __nv_bfloat16 g_As0[(size_t)NN*K2];    // h split
__device__ __align__(16) __nv_bfloat16 g_As1[(size_t)NN*K2];    // msg split
__device__ __align__(16) __nv_bfloat16 g_As2[(size_t)NN*K2];    // m1 split
__device__ __align__(16) __nv_bfloat16 g_Ast[(size_t)NL*MT*K2]; // tmp split (table)
__device__ __align__(16) __nv_bfloat16 g_Bw[(size_t)18*KB2*H + 1024];  // lin1,l2w,ilw
__device__ __align__(16) __nv_bfloat16 g_Bw2[(size_t)NL*KB2*H + 1024]; // w2
__device__ __align__(16) float g_ea[NC*G], g_C[NC];
__device__ __align__(16) __half g_Th[NL*NC*H];   // coarse fp16 filter tables
__device__ int   g_nbr[NN*KM], g_base[NN*KM], g_cnt[NN];
__device__ __align__(16) float g_w4[NN*KM*4];

__device__ __forceinline__ float sspf(float x){
    float r = (x > 0.f) ? (x + log1pf(expf(-x))) : log1pf(expf(x));
    return r - 0.69314718055994530942f;
}

// A' split store at 608-aligned blocks (dp in half2 units: 0, 304, 608)
__device__ __forceinline__ void split_store(__nv_bfloat16* base, size_t off,
                                            float v0, float v1){
    __nv_bfloat16 h0=__float2bfloat16(v0), h1=__float2bfloat16(v1);
    __nv_bfloat162 hi2; hi2.x=h0; hi2.y=h1;
    __nv_bfloat162 lo2;
    lo2.x=__float2bfloat16(v0-__bfloat162float(h0));
    lo2.y=__float2bfloat16(v1-__bfloat162float(h1));
    __nv_bfloat162* dp = reinterpret_cast<__nv_bfloat162*>(base + off);
    dp[0]   = hi2;     // k = c
    dp[304] = hi2;     // k = 608+c
    dp[608] = lo2;     // k = 1216+c
}

// ---- graph build: 1 block per node, matches jax top_k(-dist2, K); cubic weights ----
__global__ void build_graph(const float* __restrict__ pos){
    int i = blockIdx.x, b = i/NPG, il = i - b*NPG, j = threadIdx.x;
    __shared__ float sx[NPG], sy[NPG], sz[NPG], sd2[NPG];
    __shared__ int scnt;
    const float* pg = pos + (size_t)b*NPG*3;
    sx[j]=pg[j*3]; sy[j]=pg[j*3+1]; sz[j]=pg[j*3+2];
    if(j==0) scnt=0;
    __syncthreads();
    float dx=__fsub_rn(sx[il],sx[j]), dy=__fsub_rn(sy[il],sy[j]), dz=__fsub_rn(sz[il],sz[j]);
    float d2=__fadd_rn(__fadd_rn(__fmul_rn(dx,dx),__fmul_rn(dy,dy)),__fmul_rn(dz,dz));
    bool ok = (d2<=100.0f) && (j!=il);
    sd2[j] = ok ? d2 : 3.0e38f;
    __syncthreads();
    int rank=0;
    if(ok){
        #pragma unroll 8
        for(int t=0;t<NPG;t++){ float o=sd2[t]; rank += (o<d2)||(o==d2 && t<j); }
        atomicAdd(&scnt,1);
    }
    __syncthreads();
    if(j==0) g_cnt[i] = min(scnt,KM);
    if(ok && rank<KM){
        float d = sqrtf(d2);
        float u = d * (1.0f/D0);
        int s = (int)u; if(s>255) s=255; if(s<0) s=0;
        float t = u - (float)s;
        float t2=t*t, t3=t2*t;
        int e=i*KM+rank;
        g_nbr[e]=b*NPG+j; g_base[e]=s*H;
        g_w4[e*4+0]=0.5f*(-t3+2.f*t2-t);
        g_w4[e*4+1]=0.5f*(3.f*t3-5.f*t2+2.f);
        g_w4[e*4+2]=0.5f*(-3.f*t3+4.f*t2+t);
        g_w4[e*4+3]=0.5f*(t3-t2);
    }
}

// ---- gaussian smearing + cosine cutoff on coarse grid ----
__global__ void smear(){
    int idx = blockIdx.x*blockDim.x + threadIdx.x;
    if(idx >= NC*G) return;
    int q = idx/G, g = idx - q*G;
    float d = (float)(q-1)*D0;
    float step = 10.0f/49.0f;
    float x = d - (float)g*step;
    g_ea[idx] = expf((-0.5f/(step*step))*x*x);
    if(g==0) g_C[q] = 0.5f*(cosf(d*0.31415926535897932f)+1.0f);
}

// ---- embedding gather + h split ----
__global__ void embed(const float* __restrict__ emb, const int* __restrict__ z){
    int idx = blockIdx.x*blockDim.x + threadIdx.x;
    if(idx >= NN*H) return;
    int i = idx/H, c = idx - i*H;
    float v = emb[z[i]*H + c];
    g_h[idx] = v;
    __nv_bfloat16 hi = __float2bfloat16(v);
    g_As0[(size_t)i*K2 + c]        = hi;
    g_As0[(size_t)i*K2 + 608 + c]  = hi;
    g_As0[(size_t)i*K2 + 1216 + c] = __float2bfloat16(v - __bfloat162float(hi));
}

// ---- weight split: 24 [600,600] fp32 -> bf16 [hi(608);lo(608)] rows ----
__global__ void wsplit(const float* __restrict__ lin1, const float* __restrict__ l2w,
                       const float* __restrict__ ilw, const float* __restrict__ w2){
    int idx = blockIdx.x*blockDim.x + threadIdx.x;
    if(idx >= 24*H*H) return;
    int w = idx/(H*H), e = idx - w*(H*H), r = e/H, c = e - r*H;
    int l = w>>2, kind = w&3;
    const float* src = (kind==0) ? lin1 : (kind==1) ? l2w : (kind==2) ? ilw : w2;
    float v = src[(size_t)l*H*H + e];
    __nv_bfloat16 hi = __float2bfloat16(v);
    __nv_bfloat16* dst = (kind<3) ? (g_Bw + (size_t)(l*3+kind)*KB2*H)
                                  : (g_Bw2 + (size_t)l*KB2*H);
    dst[(size_t)r*H + c]        = hi;
    dst[(size_t)(608+r)*H + c]  = __float2bfloat16(v - __bfloat162float(hi));
}

// ---- aggregation: cubic interp of fp16 coarse table * fp16 x1; emits msg split ----
__global__ void __launch_bounds__(320) agg(int l){
    int i = blockIdx.x, t = threadIdx.x;
    __shared__ int s_j[KM], s_b[KM], s_cnt;
    __shared__ float4 s_w[KM];
    if(t==0) s_cnt = g_cnt[i];
    if(t<KM){
        int e=i*KM+t;
        s_j[t]=g_nbr[e]*H; s_b[t]=g_base[e];
        s_w[t]=*reinterpret_cast<const float4*>(&g_w4[e*4]);
    }
    __syncthreads();
    if(t >= 300) return;
    int h = t*2;
    const __half* T = g_Th + (size_t)l*NC*H;
    int cnt = s_cnt;
    float ax = 0.f, ay = 0.f;
    #pragma unroll 2
    for(int k=0;k<cnt;k++){
        const __half2* tp = reinterpret_cast<const __half2*>(T + s_b[k] + h);
        float2 t0=__half22float2(__ldg(tp));
        float2 t1=__half22float2(__ldg(tp+300));
        float2 t2=__half22float2(__ldg(tp+600));
        float2 t3=__half22float2(__ldg(tp+900));
        float2 x2=__half22float2(__ldg(reinterpret_cast<const __half2*>(&g_x1h[s_j[k]+h])));
        float4 w = s_w[k];
        float vx = w.x*t0.x + w.y*t1.x + w.z*t2.x + w.w*t3.x;
        float vy = w.x*t0.y + w.y*t1.y + w.z*t2.y + w.w*t3.y;
        ax = fmaf(vx, x2.x, ax);
        ay = fmaf(vy, x2.y, ay);
    }
    split_store(g_As1, (size_t)i*K2 + h, ax, ay);
}

// ---- mma / cp.async helpers ----
__device__ __forceinline__ void ldsm4(unsigned* r, unsigned addr){
    asm volatile("ldmatrix.sync.aligned.m8n8.x4.shared.b16 {%0,%1,%2,%3}, [%4];"
        : "=r"(r[0]),"=r"(r[1]),"=r"(r[2]),"=r"(r[3]) : "r"(addr));
}
__device__ __forceinline__ void ldsm4t(unsigned* r, unsigned addr){
    asm volatile("ldmatrix.sync.aligned.m8n8.x4.trans.shared.b16 {%0,%1,%2,%3}, [%4];"
        : "=r"(r[0]),"=r"(r[1]),"=r"(r[2]),"=r"(r[3]) : "r"(addr));
}
__device__ __forceinline__ void mma16816(float* c, const unsigned* a, unsigned b0, unsigned b1){
    asm volatile("mma.sync.aligned.m16n8k16.row.col.f32.bf16.bf16.f32 "
        "{%0,%1,%2,%3}, {%4,%5,%6,%7}, {%8,%9}, {%0,%1,%2,%3};"
        : "+f"(c[0]),"+f"(c[1]),"+f"(c[2]),"+f"(c[3])
        : "r"(a[0]),"r"(a[1]),"r"(a[2]),"r"(a[3]), "r"(b0),"r"(b1));
}
#define CPA16(dst,src) asm volatile("cp.async.cg.shared.global [%0], [%1], 16;\n"::"r"(dst),"l"(src))
#define CPC()  asm volatile("cp.async.commit_group;\n")
#define CPW2() asm volatile("cp.async.wait_group 2;\n" ::: "memory")
#define CPW0() asm volatile("cp.async.wait_group 0;\n" ::: "memory")

#define ASTG (32*40*2)
#define BSTG (32*72*2)

// 256 threads, 8 warps (2m x 4n), 32x64 CTA tile, warp tile 16x16, 4-stage cp.async.
struct Frag { unsigned aF[2]; unsigned bF[2]; unsigned aD, bD; };

__device__ __forceinline__ Frag make_frag(
        __nv_bfloat16 (*As)[32][40], __nv_bfloat16 (*Bs)[32][72],
        int wm, int wn, int lane, int arow, int acol, int brow, int bcol){
    Frag f;
    f.aD = (unsigned)__cvta_generic_to_shared(&As[0][arow][acol]);
    f.bD = (unsigned)__cvta_generic_to_shared(&Bs[0][brow][bcol]);
    #pragma unroll
    for(int s=0;s<2;s++)
        f.aF[s] = (unsigned)__cvta_generic_to_shared(
            &As[0][wm + (lane&15)][s*16 + (lane>>4)*8]);
    #pragma unroll
    for(int s=0;s<2;s++)
        f.bF[s] = (unsigned)__cvta_generic_to_shared(
            &Bs[0][s*16 + (lane&15)][wn + (lane>>4)*8]);
    return f;
}

// B k-block remap: blocks 0..37 identity (hi,lo), 38..56 -> hi again
__device__ __forceinline__ int bmap(int it){ return (it < 38) ? it : it - 38; }

__device__ __forceinline__ void gemm_mainloop(
        const __nv_bfloat16* aptr, const __nv_bfloat16* bptr, bool aload,
        const Frag& f, float acc[2][4]){
    if(aload) CPA16(f.aD, aptr);
    CPA16(f.bD, bptr); CPC();
    if(aload) CPA16(f.aD+ASTG, aptr+32);
    CPA16(f.bD+BSTG, bptr+(size_t)32*H); CPC();
    for(int it=0; it<NIT; it++){
        int pre = it+2;
        if(pre < NIT){
            int sb = pre & 3;
            if(aload) CPA16(f.aD + sb*ASTG, aptr + pre*32);
            CPA16(f.bD + sb*BSTG, bptr + (size_t)(bmap(pre)*32)*H);
        }
        CPC();
        if(it < NIT-2) CPW2(); else CPW0();
        __syncthreads();
        unsigned ao = (it&3)*ASTG, bo = (it&3)*BSTG;
        #pragma unroll
        for(int s=0;s<2;s++){
            unsigned af[4], bf[4];
            ldsm4 (af, f.aF[s] + ao);
            ldsm4t(bf, f.bF[s] + bo);
            mma16816(acc[0], af, bf[0], bf[1]);
            mma16816(acc[1], af, bf[2], bf[3]);
        }
    }
}

// ---- node GEMM: C[1024,600] = A'[1024,1824] @ B'[1216,600](remapped), fused epi ----
// EPI 0: -> x1h fp16. EPI 1: ssp(+bias) -> split sout. EPI 2: +bias+h residual -> h & split.
template<int EPI>
__global__ void __launch_bounds__(256) bgemm(const __nv_bfloat16* __restrict__ Ap,
        const __nv_bfloat16* __restrict__ Bp, const float* __restrict__ bias,
        float* __restrict__ hbuf, __nv_bfloat16* __restrict__ sout,
        __half* __restrict__ x1out){
    __shared__ __nv_bfloat16 As[4][32][40];
    __shared__ __nv_bfloat16 Bs[4][32][72];
    int tid=threadIdx.x, warp=tid>>5, lane=tid&31;
    int m0=blockIdx.y*32, n0=blockIdx.x*64;
    int wm=(warp>>2)*16, wn=(warp&3)*16;
    int arow=(tid&127)>>2, acol=(tid&3)*8;
    int brow=tid>>3, bcol=(tid&7)*8;
    bool aload = tid < 128;
    Frag f = make_frag(As, Bs, wm, wn, lane, arow, acol, brow, bcol);
    float acc[2][4];
    #pragma unroll
    for(int ni=0;ni<2;ni++)
        #pragma unroll
        for(int q=0;q<4;q++) acc[ni][q]=0.f;
    const __nv_bfloat16* aptr = Ap + (size_t)(m0+arow)*K2 + acol;
    const __nv_bfloat16* bptr = Bp + (size_t)brow*H + n0 + bcol;
    gemm_mainloop(aptr, bptr, aload, f, acc);

    #pragma unroll
    for(int ni=0;ni<2;ni++){
        int c0 = n0 + wn + ni*8 + (lane&3)*2;
        if(c0 >= 600) continue;
        #pragma unroll
        for(int hf=0; hf<2; hf++){
            int r = m0 + wm + (lane>>2) + hf*8;
            float v0 = acc[ni][hf*2], v1 = acc[ni][hf*2+1];
            if(EPI==0){
                *reinterpret_cast<__half2*>(x1out + (size_t)r*H + c0)
                    = __floats2half2_rn(v0, v1);
            } else {
                v0 += bias[c0]; v1 += bias[c0+1];
                if(EPI==1){
                    v0 = sspf(v0); v1 = sspf(v1);
                } else {
                    float2 hv = *reinterpret_cast<float2*>(hbuf + (size_t)r*H + c0);
                    v0 += hv.x; v1 += hv.y;
                    *reinterpret_cast<float2*>(hbuf + (size_t)r*H + c0) = make_float2(v0, v1);
                }
                split_store(sout, (size_t)r*K2 + c0, v0, v1);
            }
        }
    }
}

// ---- table GEMM: per layer, T = (tmp' @ w2' + b2) * C -> fp16 table ----
__global__ void __launch_bounds__(256) tbgemm(const float* __restrict__ b2){
    __shared__ __nv_bfloat16 As[4][32][40];
    __shared__ __nv_bfloat16 Bs[4][32][72];
    int zb = blockIdx.z;
    int tid=threadIdx.x, warp=tid>>5, lane=tid&31;
    int m0=blockIdx.y*32, n0=blockIdx.x*64;
    int wm=(warp>>2)*16, wn=(warp&3)*16;
    int arow=(tid&127)>>2, acol=(tid&3)*8;
    int brow=tid>>3, bcol=(tid&7)*8;
    bool aload = tid < 128;
    Frag f = make_frag(As, Bs, wm, wn, lane, arow, acol, brow, bcol);
    float acc[2][4];
    #pragma unroll
    for(int ni=0;ni<2;ni++)
        #pragma unroll
        for(int q=0;q<4;q++) acc[ni][q]=0.f;
    const __nv_bfloat16* aptr = g_Ast + (size_t)zb*MT*K2 + (size_t)(m0+arow)*K2 + acol;
    const __nv_bfloat16* bptr = g_Bw2 + (size_t)zb*KB2*H + (size_t)brow*H + n0 + bcol;
    gemm_mainloop(aptr, bptr, aload, f, acc);

    const float* bias = b2 + (size_t)zb*H;
    #pragma unroll
    for(int ni=0;ni<2;ni++){
        int c0 = n0 + wn + ni*8 + (lane&3)*2;
        if(c0 >= 600) continue;
        #pragma unroll
        for(int hf=0; hf<2; hf++){
            int r = m0 + wm + (lane>>2) + hf*8;
            if(r >= NC) continue;
            float cc = g_C[r];
            float v0 = (acc[ni][hf*2]   + bias[c0])   * cc;
            float v1 = (acc[ni][hf*2+1] + bias[c0+1]) * cc;
            *reinterpret_cast<__half2*>(g_Th + (size_t)zb*NC*H + (size_t)r*H + c0)
                = __floats2half2_rn(v0, v1);
        }
    }
}

// ---- table stage-1 (K=50) FFMA GEMM, epilogue: ssp + direct bf16 split ----
__global__ void __launch_bounds__(256) sgemm1(const float* __restrict__ w1,
        const float* __restrict__ b1){
    int zb = blockIdx.z;
    const float* A = g_ea;
    const float* B = w1 + (size_t)zb*G*H;
    const float* bias = b1 + (size_t)zb*H;
    const int BM=64, BN=64, BK=10;
    __shared__ float As[BK][BM], Bs[BK][BN];
    int tid=threadIdx.x, tx=tid&15, ty=tid>>4;
    int m0=blockIdx.y*BM, n0=blockIdx.x*BN;
    int ar=tid&63, ac=tid>>6;
    int br=tid>>6, bc=(tid&63);
    float acc[4][4];
    #pragma unroll
    for(int a=0;a<4;a++)
        #pragma unroll
        for(int c=0;c<4;c++) acc[a][c]=0.f;
    for(int k0=0;k0<G;k0+=BK){
        #pragma unroll
        for(int u=0;u<3;u++){
            int kk = ac + u*4;
            if(kk<BK){
                int gm=m0+ar, gk=k0+kk;
                As[kk][ar] = (gm<NC && gk<G) ? A[(size_t)gm*G+gk] : 0.f;
            }
        }
        #pragma unroll
        for(int u=0;u<3;u++){
            int kk = br + u*4;
            if(kk<BK){
                int gk=k0+kk, gn=n0+bc;
                Bs[kk][bc] = (gk<G && gn<H) ? B[(size_t)gk*H+gn] : 0.f;
            }
        }
        __syncthreads();
        #pragma unroll
        for(int kk=0;kk<BK;kk++){
            float4 av=*reinterpret_cast<const float4*>(&As[kk][ty<<2]);
            float4 bv=*reinterpret_cast<const float4*>(&Bs[kk][tx<<2]);
            float a0=av.x,a1=av.y,a2=av.z,a3=av.w;
            float b0=bv.x,b1=bv.y,b2=bv.z,b3=bv.w;
            acc[0][0]=fmaf(a0,b0,acc[0][0]); acc[0][1]=fmaf(a0,b1,acc[0][1]);
            acc[0][2]=fmaf(a0,b2,acc[0][2]); acc[0][3]=fmaf(a0,b3,acc[0][3]);
            acc[1][0]=fmaf(a1,b0,acc[1][0]); acc[1][1]=fmaf(a1,b1,acc[1][1]);
            acc[1][2]=fmaf(a1,b2,acc[1][2]); acc[1][3]=fmaf(a1,b3,acc[1][3]);
            acc[2][0]=fmaf(a2,b0,acc[2][0]); acc[2][1]=fmaf(a2,b1,acc[2][1]);
            acc[2][2]=fmaf(a2,b2,acc[2][2]); acc[2][3]=fmaf(a2,b3,acc[2][3]);
            acc[3][0]=fmaf(a3,b0,acc[3][0]); acc[3][1]=fmaf(a3,b1,acc[3][1]);
            acc[3][2]=fmaf(a3,b2,acc[3][2]); acc[3][3]=fmaf(a3,b3,acc[3][3]);
        }
        __syncthreads();
    }
    #pragma unroll
    for(int ii=0;ii<4;ii++){
        int m=m0+(ty<<2)+ii;
        if(m>=NC) continue;
        __nv_bfloat16* row = g_Ast + (size_t)(zb*MT + m)*K2;
        #pragma unroll
        for(int jj=0;jj<4;jj++){
            int n=n0+(tx<<2)+jj;
            if(n>=H) continue;
            float v = sspf(acc[ii][jj] + bias[n]);
            __nv_bfloat16 hi = __float2bfloat16(v);
            row[n]        = hi;
            row[608 + n]  = hi;
            row[1216 + n] = __float2bfloat16(v - __bfloat162float(hi));
        }
    }
}

// ---- fused mean-pool + final linear ----
__global__ void __launch_bounds__(600) poolfin(const float* __restrict__ pw,
        const float* __restrict__ pb, float* __restrict__ out){
    int b = blockIdx.x, h = threadIdx.x;
    __shared__ float sp[H];
    const float* p = g_h + (size_t)b*NPG*H + h;
    float s = 0.f;
    #pragma unroll 8
    for(int n=0;n<NPG;n++) s += p[(size_t)n*H];
    sp[h] = s * (1.0f/NPG);
    __syncthreads();
    float o = pb[h];
    for(int k=0;k<H;k++) o = fmaf(sp[k], pw[(size_t)k*H+h], o);
    out[(size_t)b*H + h] = o;
}

extern "C" void kernel_launch(void* const* d_in, const int* in_sizes, int n_in,
                              void* d_out, int out_size){
    // dict order: z,pos,emb,w1,b1,w2,b2,lin1,l2w,l2b,ilw,ilb,pw,pb
    int map[14] = {0,1,2,3,4,5,6,7,8,9,10,11,12,13};
    if(!(in_sizes[0]==1024 && in_sizes[1]==3072)){
        int sig[14] = {13,0,1,2,3,4,5,6,7,8,9,10,11,12};
        for(int i=0;i<14;i++) map[i]=sig[i];
    }
    const int*   z    = (const int*)  d_in[map[0]];
    const float* posv = (const float*)d_in[map[1]];
    const float* emb  = (const float*)d_in[map[2]];
    const float* w1   = (const float*)d_in[map[3]];
    const float* b1   = (const float*)d_in[map[4]];
    const float* w2   = (const float*)d_in[map[5]];
    const float* b2   = (const float*)d_in[map[6]];
    const float* lin1 = (const float*)d_in[map[7]];
    const float* l2w  = (const float*)d_in[map[8]];
    const float* l2b  = (const float*)d_in[map[9]];
    const float* ilw  = (const float*)d_in[map[10]];
    const float* ilb  = (const float*)d_in[map[11]];
    const float* pw   = (const float*)d_in[map[12]];
    const float* pb   = (const float*)d_in[map[13]];
    float* out = (float*)d_out;

    float *p_h;
    __nv_bfloat16 *p_As0,*p_As1,*p_As2,*p_Bw;
    __half *p_x1h;
    cudaGetSymbolAddress((void**)&p_h,   g_h);
    cudaGetSymbolAddress((void**)&p_As0, g_As0);
    cudaGetSymbolAddress((void**)&p_As1, g_As1);
    cudaGetSymbolAddress((void**)&p_As2, g_As2);
    cudaGetSymbolAddress((void**)&p_Bw,  g_Bw);
    cudaGetSymbolAddress((void**)&p_x1h, g_x1h);

    build_graph<<<NN, NPG>>>(posv);
    smear<<<(NC*G+255)/256, 256>>>();
    embed<<<(NN*H+255)/256, 256>>>(emb, z);
    wsplit<<<(24*H*H+255)/256, 256>>>(lin1, l2w, ilw, w2);

    // table build: stage-1 FFMA (K=50, fused split) -> tensor-core stage-2
    dim3 gT1((H+63)/64, (NC+63)/64, NL);
    sgemm1<<<gT1, 256>>>(w1, b1);
    dim3 gTB((H+63)/64, MT/32, NL);   // 10 x 10 x 6
    tbgemm<<<gTB, 256>>>(b2);

    dim3 gG(10, 32);   // 320 blocks
    for(int l=0;l<NL;l++){
        const __nv_bfloat16* Blin1 = p_Bw + (size_t)(l*3+0)*KB2*H;
        const __nv_bfloat16* Bl2w  = p_Bw + (size_t)(l*3+1)*KB2*H;
        const __nv_bfloat16* Bilw  = p_Bw + (size_t)(l*3+2)*KB2*H;
        bgemm<0><<<gG,256>>>(p_As0, Blin1, nullptr, nullptr, nullptr, p_x1h);
        agg<<<NN, 320>>>(l);
        bgemm<1><<<gG,256>>>(p_As1, Bl2w, l2b+(size_t)l*H, nullptr, p_As2, nullptr);
        bgemm<2><<<gG,256>>>(p_As2, Bilw, ilb+(size_t)l*H, p_h, p_As0, nullptr);
    }
    poolfin<<<NB, H>>>(pw, pb, out);
}

// round 12
// speedup vs baseline: 2.1697x; 1.3771x over previous
#include <cuda_runtime.h>
#include <cuda_fp16.h>
#include <math.h>

#define NN 1024
#define NPG 128
#define NB 8
#define KM 64
#define H 600
#define G 50
#define NL 6
#define NC 259           // coarse knots, d=(q-1)*D0, q=0..258
#define D0 (10.0f/256.0f)
#define HK 608           // one split block (600 padded to 19*32)
#define K2 1216          // A' width: [hi(608) | lo(608)]
#define NIT2 38          // K2/32 (2-term)
#define NIT1 19          // HK/32 (1-term, bgemm0)
#define MT 320           // padded M for table gemm

// ---------------- device scratch (zero-initialized at module load) ----------------
__device__ __align__(16) float g_h[NN*H];
__device__ __align__(16) __half g_x1h[NN*H];
__device__ __align__(16) __half g_As0[(size_t)NN*K2];    // h split
__device__ __align__(16) __half g_As1[(size_t)NN*K2];    // msg split
__device__ __align__(16) __half g_As2[(size_t)NN*K2];    // m1 split
__device__ __align__(16) __half g_Ast[(size_t)NL*MT*K2]; // tmp split (table)
__device__ __align__(16) __half g_Bw[(size_t)18*HK*H + 1024];  // lin1,l2w,ilw (fp16)
__device__ __align__(16) __half g_Bw2[(size_t)NL*HK*H + 1024]; // w2 (fp16)
__device__ __align__(16) float g_ea[NC*G], g_C[NC];
__device__ __align__(16) __half g_Th[NL*NC*H];   // coarse fp16 filter tables
__device__ int   g_nbr[NN*KM], g_base[NN*KM], g_cnt[NN];
__device__ __align__(16) float g_w4[NN*KM*4];

__device__ __forceinline__ float sspf(float x){
    float r = (x > 0.f) ? (x + log1pf(expf(-x))) : log1pf(expf(x));
    return r - 0.69314718055994530942f;
}

// A' split store: hi block at 0, lo block at +608 (half2 units: 0, 304)
__device__ __forceinline__ void split_store(__half* base, size_t off,
                                            float v0, float v1){
    __half2 hi2 = __floats2half2_rn(v0, v1);
    __half2 lo2 = __floats2half2_rn(v0 - __half2float(__low2half(hi2)),
                                    v1 - __half2float(__high2half(hi2)));
    __half2* dp = reinterpret_cast<__half2*>(base + off);
    dp[0]   = hi2;
    dp[304] = lo2;
}

// ---- graph build: 1 block per node, matches jax top_k(-dist2, K); cubic weights ----
__global__ void build_graph(const float* __restrict__ pos){
    int i = blockIdx.x, b = i/NPG, il = i - b*NPG, j = threadIdx.x;
    __shared__ float sx[NPG], sy[NPG], sz[NPG], sd2[NPG];
    __shared__ int scnt;
    const float* pg = pos + (size_t)b*NPG*3;
    sx[j]=pg[j*3]; sy[j]=pg[j*3+1]; sz[j]=pg[j*3+2];
    if(j==0) scnt=0;
    __syncthreads();
    float dx=__fsub_rn(sx[il],sx[j]), dy=__fsub_rn(sy[il],sy[j]), dz=__fsub_rn(sz[il],sz[j]);
    float d2=__fadd_rn(__fadd_rn(__fmul_rn(dx,dx),__fmul_rn(dy,dy)),__fmul_rn(dz,dz));
    bool ok = (d2<=100.0f) && (j!=il);
    sd2[j] = ok ? d2 : 3.0e38f;
    __syncthreads();
    int rank=0;
    if(ok){
        #pragma unroll 8
        for(int t=0;t<NPG;t++){ float o=sd2[t]; rank += (o<d2)||(o==d2 && t<j); }
        atomicAdd(&scnt,1);
    }
    __syncthreads();
    if(j==0) g_cnt[i] = min(scnt,KM);
    if(ok && rank<KM){
        float d = sqrtf(d2);
        float u = d * (1.0f/D0);
        int s = (int)u; if(s>255) s=255; if(s<0) s=0;
        float t = u - (float)s;
        float t2=t*t, t3=t2*t;
        int e=i*KM+rank;
        g_nbr[e]=b*NPG+j; g_base[e]=s*H;
        g_w4[e*4+0]=0.5f*(-t3+2.f*t2-t);
        g_w4[e*4+1]=0.5f*(3.f*t3-5.f*t2+2.f);
        g_w4[e*4+2]=0.5f*(-3.f*t3+4.f*t2+t);
        g_w4[e*4+3]=0.5f*(t3-t2);
    }
}

// ---- gaussian smearing + cosine cutoff on coarse grid ----
__global__ void smear(){
    int idx = blockIdx.x*blockDim.x + threadIdx.x;
    if(idx >= NC*G) return;
    int q = idx/G, g = idx - q*G;
    float d = (float)(q-1)*D0;
    float step = 10.0f/49.0f;
    float x = d - (float)g*step;
    g_ea[idx] = expf((-0.5f/(step*step))*x*x);
    if(g==0) g_C[q] = 0.5f*(cosf(d*0.31415926535897932f)+1.0f);
}

// ---- embedding gather + h split ----
__global__ void embed(const float* __restrict__ emb, const int* __restrict__ z){
    int idx = blockIdx.x*blockDim.x + threadIdx.x;
    if(idx >= NN*H) return;
    int i = idx/H, c = idx - i*H;
    float v = emb[z[i]*H + c];
    g_h[idx] = v;
    __half hi = __float2half_rn(v);
    g_As0[(size_t)i*K2 + c]      = hi;
    g_As0[(size_t)i*K2 + HK + c] = __float2half_rn(v - __half2float(hi));
}

// ---- weight convert: 24 [600,600] fp32 -> fp16 (vectorized by 2) ----
__global__ void wsplit(const float* __restrict__ lin1, const float* __restrict__ l2w,
                       const float* __restrict__ ilw, const float* __restrict__ w2){
    int idx = blockIdx.x*blockDim.x + threadIdx.x;
    const int PM = H*H/2;   // 180000 half2 per matrix
    if(idx >= 24*PM) return;
    int w = idx/PM, e2 = idx - w*PM;
    int r = e2/300, c = (e2 - r*300)*2;
    int l = w>>2, kind = w&3;
    const float* src = (kind==0) ? lin1 : (kind==1) ? l2w : (kind==2) ? ilw : w2;
    float2 v = *reinterpret_cast<const float2*>(src + (size_t)l*H*H + (size_t)r*H + c);
    __half* dst = (kind<3) ? (g_Bw + (size_t)(l*3+kind)*HK*H)
                           : (g_Bw2 + (size_t)l*HK*H);
    *reinterpret_cast<__half2*>(dst + (size_t)r*H + c) = __floats2half2_rn(v.x, v.y);
}

// ---- aggregation: cubic interp of fp16 coarse table * fp16 x1; emits msg split ----
__global__ void __launch_bounds__(320) agg(int l){
    int i = blockIdx.x, t = threadIdx.x;
    __shared__ int s_j[KM], s_b[KM], s_cnt;
    __shared__ float4 s_w[KM];
    if(t==0) s_cnt = g_cnt[i];
    if(t<KM){
        int e=i*KM+t;
        s_j[t]=g_nbr[e]*H; s_b[t]=g_base[e];
        s_w[t]=*reinterpret_cast<const float4*>(&g_w4[e*4]);
    }
    __syncthreads();
    if(t >= 300) return;
    int h = t*2;
    const __half* T = g_Th + (size_t)l*NC*H;
    int cnt = s_cnt;
    float ax = 0.f, ay = 0.f;
    #pragma unroll 2
    for(int k=0;k<cnt;k++){
        const __half2* tp = reinterpret_cast<const __half2*>(T + s_b[k] + h);
        float2 t0=__half22float2(__ldg(tp));
        float2 t1=__half22float2(__ldg(tp+300));
        float2 t2=__half22float2(__ldg(tp+600));
        float2 t3=__half22float2(__ldg(tp+900));
        float2 x2=__half22float2(__ldg(reinterpret_cast<const __half2*>(&g_x1h[s_j[k]+h])));
        float4 w = s_w[k];
        float vx = w.x*t0.x + w.y*t1.x + w.z*t2.x + w.w*t3.x;
        float vy = w.x*t0.y + w.y*t1.y + w.z*t2.y + w.w*t3.y;
        ax = fmaf(vx, x2.x, ax);
        ay = fmaf(vy, x2.y, ay);
    }
    split_store(g_As1, (size_t)i*K2 + h, ax, ay);
}

// ---- mma / cp.async helpers ----
__device__ __forceinline__ void ldsm4(unsigned* r, unsigned addr){
    asm volatile("ldmatrix.sync.aligned.m8n8.x4.shared.b16 {%0,%1,%2,%3}, [%4];"
        : "=r"(r[0]),"=r"(r[1]),"=r"(r[2]),"=r"(r[3]) : "r"(addr));
}
__device__ __forceinline__ void ldsm4t(unsigned* r, unsigned addr){
    asm volatile("ldmatrix.sync.aligned.m8n8.x4.trans.shared.b16 {%0,%1,%2,%3}, [%4];"
        : "=r"(r[0]),"=r"(r[1]),"=r"(r[2]),"=r"(r[3]) : "r"(addr));
}
__device__ __forceinline__ void mma16816(float* c, const unsigned* a, unsigned b0, unsigned b1){
    asm volatile("mma.sync.aligned.m16n8k16.row.col.f32.f16.f16.f32 "
        "{%0,%1,%2,%3}, {%4,%5,%6,%7}, {%8,%9}, {%0,%1,%2,%3};"
        : "+f"(c[0]),"+f"(c[1]),"+f"(c[2]),"+f"(c[3])
        : "r"(a[0]),"r"(a[1]),"r"(a[2]),"r"(a[3]), "r"(b0),"r"(b1));
}
#define CPA16(dst,src) asm volatile("cp.async.cg.shared.global [%0], [%1], 16;\n"::"r"(dst),"l"(src))
#define CPC()  asm volatile("cp.async.commit_group;\n")
#define CPW2() asm volatile("cp.async.wait_group 2;\n" ::: "memory")
#define CPW0() asm volatile("cp.async.wait_group 0;\n" ::: "memory")

#define ASTG (32*40*2)
#define BSTG (32*72*2)

// 256 threads, 8 warps (2m x 4n), 32x64 CTA tile, warp tile 16x16, 4-stage cp.async.
struct Frag { unsigned aF[2]; unsigned bF[2]; unsigned aD, bD; };

__device__ __forceinline__ Frag make_frag(
        __half (*As)[32][40], __half (*Bs)[32][72],
        int wm, int wn, int lane, int arow, int acol, int brow, int bcol){
    Frag f;
    f.aD = (unsigned)__cvta_generic_to_shared(&As[0][arow][acol]);
    f.bD = (unsigned)__cvta_generic_to_shared(&Bs[0][brow][bcol]);
    #pragma unroll
    for(int s=0;s<2;s++)
        f.aF[s] = (unsigned)__cvta_generic_to_shared(
            &As[0][wm + (lane&15)][s*16 + (lane>>4)*8]);
    #pragma unroll
    for(int s=0;s<2;s++)
        f.bF[s] = (unsigned)__cvta_generic_to_shared(
            &Bs[0][s*16 + (lane&15)][wn + (lane>>4)*8]);
    return f;
}

// NITER k-blocks over A; B has 19 blocks, reused for blocks 19..37
template<int NITER>
__device__ __forceinline__ void gemm_mainloop(
        const __half* aptr, const __half* bptr, bool aload,
        const Frag& f, float acc[2][4]){
    if(aload) CPA16(f.aD, aptr);
    CPA16(f.bD, bptr); CPC();
    if(aload) CPA16(f.aD+ASTG, aptr+32);
    CPA16(f.bD+BSTG, bptr+(size_t)32*H); CPC();
    for(int it=0; it<NITER; it++){
        int pre = it+2;
        if(pre < NITER){
            int sb = pre & 3;
            int bm = (pre < 19) ? pre : pre - 19;
            if(aload) CPA16(f.aD + sb*ASTG, aptr + pre*32);
            CPA16(f.bD + sb*BSTG, bptr + (size_t)(bm*32)*H);
        }
        CPC();
        if(it < NITER-2) CPW2(); else CPW0();
        __syncthreads();
        unsigned ao = (it&3)*ASTG, bo = (it&3)*BSTG;
        #pragma unroll
        for(int s=0;s<2;s++){
            unsigned af[4], bf[4];
            ldsm4 (af, f.aF[s] + ao);
            ldsm4t(bf, f.bF[s] + bo);
            mma16816(acc[0], af, bf[0], bf[1]);
            mma16816(acc[1], af, bf[2], bf[3]);
        }
    }
}

// ---- node GEMM with fused epilogue ----
// EPI 0: -> x1h fp16 (single-term A). EPI 1: ssp(+bias) -> split. EPI 2: +bias+h residual -> h & split.
template<int EPI, int NITER>
__global__ void __launch_bounds__(256) bgemm(const __half* __restrict__ Ap,
        const __half* __restrict__ Bp, const float* __restrict__ bias,
        float* __restrict__ hbuf, __half* __restrict__ sout,
        __half* __restrict__ x1out){
    __shared__ __half As[4][32][40];
    __shared__ __half Bs[4][32][72];
    int tid=threadIdx.x, warp=tid>>5, lane=tid&31;
    int m0=blockIdx.y*32, n0=blockIdx.x*64;
    int wm=(warp>>2)*16, wn=(warp&3)*16;
    int arow=(tid&127)>>2, acol=(tid&3)*8;
    int brow=tid>>3, bcol=(tid&7)*8;
    bool aload = tid < 128;
    Frag f = make_frag(As, Bs, wm, wn, lane, arow, acol, brow, bcol);
    float acc[2][4];
    #pragma unroll
    for(int ni=0;ni<2;ni++)
        #pragma unroll
        for(int q=0;q<4;q++) acc[ni][q]=0.f;
    const __half* aptr = Ap + (size_t)(m0+arow)*K2 + acol;
    const __half* bptr = Bp + (size_t)brow*H + n0 + bcol;
    gemm_mainloop<NITER>(aptr, bptr, aload, f, acc);

    #pragma unroll
    for(int ni=0;ni<2;ni++){
        int c0 = n0 + wn + ni*8 + (lane&3)*2;
        if(c0 >= 600) continue;
        #pragma unroll
        for(int hf=0; hf<2; hf++){
            int r = m0 + wm + (lane>>2) + hf*8;
            float v0 = acc[ni][hf*2], v1 = acc[ni][hf*2+1];
            if(EPI==0){
                *reinterpret_cast<__half2*>(x1out + (size_t)r*H + c0)
                    = __floats2half2_rn(v0, v1);
            } else {
                v0 += bias[c0]; v1 += bias[c0+1];
                if(EPI==1){
                    v0 = sspf(v0); v1 = sspf(v1);
                } else {
                    float2 hv = *reinterpret_cast<float2*>(hbuf + (size_t)r*H + c0);
                    v0 += hv.x; v1 += hv.y;
                    *reinterpret_cast<float2*>(hbuf + (size_t)r*H + c0) = make_float2(v0, v1);
                }
                split_store(sout, (size_t)r*K2 + c0, v0, v1);
            }
        }
    }
}

// ---- table GEMM: per layer, T = (tmp' @ w2 + b2) * C -> fp16 table ----
__global__ void __launch_bounds__(256) tbgemm(const float* __restrict__ b2){
    __shared__ __half As[4][32][40];
    __shared__ __half Bs[4][32][72];
    int zb = blockIdx.z;
    int tid=threadIdx.x, warp=tid>>5, lane=tid&31;
    int m0=blockIdx.y*32, n0=blockIdx.x*64;
    int wm=(warp>>2)*16, wn=(warp&3)*16;
    int arow=(tid&127)>>2, acol=(tid&3)*8;
    int brow=tid>>3, bcol=(tid&7)*8;
    bool aload = tid < 128;
    Frag f = make_frag(As, Bs, wm, wn, lane, arow, acol, brow, bcol);
    float acc[2][4];
    #pragma unroll
    for(int ni=0;ni<2;ni++)
        #pragma unroll
        for(int q=0;q<4;q++) acc[ni][q]=0.f;
    const __half* aptr = g_Ast + (size_t)zb*MT*K2 + (size_t)(m0+arow)*K2 + acol;
    const __half* bptr = g_Bw2 + (size_t)zb*HK*H + (size_t)brow*H + n0 + bcol;
    gemm_mainloop<NIT2>(aptr, bptr, aload, f, acc);

    const float* bias = b2 + (size_t)zb*H;
    #pragma unroll
    for(int ni=0;ni<2;ni++){
        int c0 = n0 + wn + ni*8 + (lane&3)*2;
        if(c0 >= 600) continue;
        #pragma unroll
        for(int hf=0; hf<2; hf++){
            int r = m0 + wm + (lane>>2) + hf*8;
            if(r >= NC) continue;
            float cc = g_C[r];
            float v0 = (acc[ni][hf*2]   + bias[c0])   * cc;
            float v1 = (acc[ni][hf*2+1] + bias[c0+1]) * cc;
            *reinterpret_cast<__half2*>(g_Th + (size_t)zb*NC*H + (size_t)r*H + c0)
                = __floats2half2_rn(v0, v1);
        }
    }
}

// ---- table stage-1 (K=50) FFMA GEMM, epilogue: ssp + direct fp16 split ----
__global__ void __launch_bounds__(256) sgemm1(const float* __restrict__ w1,
        const float* __restrict__ b1){
    int zb = blockIdx.z;
    const float* A = g_ea;
    const float* B = w1 + (size_t)zb*G*H;
    const float* bias = b1 + (size_t)zb*H;
    const int BM=64, BN=64, BK=10;
    __shared__ float As[BK][BM], Bs[BK][BN];
    int tid=threadIdx.x, tx=tid&15, ty=tid>>4;
    int m0=blockIdx.y*BM, n0=blockIdx.x*BN;
    int ar=tid&63, ac=tid>>6;
    int br=tid>>6, bc=(tid&63);
    float acc[4][4];
    #pragma unroll
    for(int a=0;a<4;a++)
        #pragma unroll
        for(int c=0;c<4;c++) acc[a][c]=0.f;
    for(int k0=0;k0<G;k0+=BK){
        #pragma unroll
        for(int u=0;u<3;u++){
            int kk = ac + u*4;
            if(kk<BK){
                int gm=m0+ar, gk=k0+kk;
                As[kk][ar] = (gm<NC && gk<G) ? A[(size_t)gm*G+gk] : 0.f;
            }
        }
        #pragma unroll
        for(int u=0;u<3;u++){
            int kk = br + u*4;
            if(kk<BK){
                int gk=k0+kk, gn=n0+bc;
                Bs[kk][bc] = (gk<G && gn<H) ? B[(size_t)gk*H+gn] : 0.f;
            }
        }
        __syncthreads();
        #pragma unroll
        for(int kk=0;kk<BK;kk++){
            float4 av=*reinterpret_cast<const float4*>(&As[kk][ty<<2]);
            float4 bv=*reinterpret_cast<const float4*>(&Bs[kk][tx<<2]);
            float a0=av.x,a1=av.y,a2=av.z,a3=av.w;
            float b0=bv.x,b1=bv.y,b2=bv.z,b3=bv.w;
            acc[0][0]=fmaf(a0,b0,acc[0][0]); acc[0][1]=fmaf(a0,b1,acc[0][1]);
            acc[0][2]=fmaf(a0,b2,acc[0][2]); acc[0][3]=fmaf(a0,b3,acc[0][3]);
            acc[1][0]=fmaf(a1,b0,acc[1][0]); acc[1][1]=fmaf(a1,b1,acc[1][1]);
            acc[1][2]=fmaf(a1,b2,acc[1][2]); acc[1][3]=fmaf(a1,b3,acc[1][3]);
            acc[2][0]=fmaf(a2,b0,acc[2][0]); acc[2][1]=fmaf(a2,b1,acc[2][1]);
            acc[2][2]=fmaf(a2,b2,acc[2][2]); acc[2][3]=fmaf(a2,b3,acc[2][3]);
            acc[3][0]=fmaf(a3,b0,acc[3][0]); acc[3][1]=fmaf(a3,b1,acc[3][1]);
            acc[3][2]=fmaf(a3,b2,acc[3][2]); acc[3][3]=fmaf(a3,b3,acc[3][3]);
        }
        __syncthreads();
    }
    #pragma unroll
    for(int ii=0;ii<4;ii++){
        int m=m0+(ty<<2)+ii;
        if(m>=NC) continue;
        __half* row = g_Ast + (size_t)(zb*MT + m)*K2;
        #pragma unroll
        for(int jj=0;jj<4;jj++){
            int n=n0+(tx<<2)+jj;
            if(n>=H) continue;
            float v = sspf(acc[ii][jj] + bias[n]);
            __half hi = __float2half_rn(v);
            row[n]      = hi;
            row[HK + n] = __float2half_rn(v - __half2float(hi));
        }
    }
}

// ---- fused mean-pool + final linear ----
__global__ void __launch_bounds__(600) poolfin(const float* __restrict__ pw,
        const float* __restrict__ pb, float* __restrict__ out){
    int b = blockIdx.x, h = threadIdx.x;
    __shared__ float sp[H];
    const float* p = g_h + (size_t)b*NPG*H + h;
    float s = 0.f;
    #pragma unroll 8
    for(int n=0;n<NPG;n++) s += p[(size_t)n*H];
    sp[h] = s * (1.0f/NPG);
    __syncthreads();
    float o = pb[h];
    for(int k=0;k<H;k++) o = fmaf(sp[k], pw[(size_t)k*H+h], o);
    out[(size_t)b*H + h] = o;
}

extern "C" void kernel_launch(void* const* d_in, const int* in_sizes, int n_in,
                              void* d_out, int out_size){
    // dict order: z,pos,emb,w1,b1,w2,b2,lin1,l2w,l2b,ilw,ilb,pw,pb
    int map[14] = {0,1,2,3,4,5,6,7,8,9,10,11,12,13};
    if(!(in_sizes[0]==1024 && in_sizes[1]==3072)){
        int sig[14] = {13,0,1,2,3,4,5,6,7,8,9,10,11,12};
        for(int i=0;i<14;i++) map[i]=sig[i];
    }
    const int*   z    = (const int*)  d_in[map[0]];
    const float* posv = (const float*)d_in[map[1]];
    const float* emb  = (const float*)d_in[map[2]];
    const float* w1   = (const float*)d_in[map[3]];
    const float* b1   = (const float*)d_in[map[4]];
    const float* w2   = (const float*)d_in[map[5]];
    const float* b2   = (const float*)d_in[map[6]];
    const float* lin1 = (const float*)d_in[map[7]];
    const float* l2w  = (const float*)d_in[map[8]];
    const float* l2b  = (const float*)d_in[map[9]];
    const float* ilw  = (const float*)d_in[map[10]];
    const float* ilb  = (const float*)d_in[map[11]];
    const float* pw   = (const float*)d_in[map[12]];
    const float* pb   = (const float*)d_in[map[13]];
    float* out = (float*)d_out;

    float *p_h;
    __half *p_As0,*p_As1,*p_As2,*p_Bw,*p_x1h;
    cudaGetSymbolAddress((void**)&p_h,   g_h);
    cudaGetSymbolAddress((void**)&p_As0, g_As0);
    cudaGetSymbolAddress((void**)&p_As1, g_As1);
    cudaGetSymbolAddress((void**)&p_As2, g_As2);
    cudaGetSymbolAddress((void**)&p_Bw,  g_Bw);
    cudaGetSymbolAddress((void**)&p_x1h, g_x1h);

    build_graph<<<NN, NPG>>>(posv);
    smear<<<(NC*G+255)/256, 256>>>();
    embed<<<(NN*H+255)/256, 256>>>(emb, z);
    wsplit<<<(24*H*H/2+255)/256, 256>>>(lin1, l2w, ilw, w2);

    // table build: stage-1 FFMA (K=50, fused split) -> tensor-core stage-2
    dim3 gT1((H+63)/64, (NC+63)/64, NL);
    sgemm1<<<gT1, 256>>>(w1, b1);
    dim3 gTB((H+63)/64, MT/32, NL);   // 10 x 10 x 6
    tbgemm<<<gTB, 256>>>(b2);

    dim3 gG(10, 32);   // 320 blocks
    for(int l=0;l<NL;l++){
        const __half* Blin1 = p_Bw + (size_t)(l*3+0)*HK*H;
        const __half* Bl2w  = p_Bw + (size_t)(l*3+1)*HK*H;
        const __half* Bilw  = p_Bw + (size_t)(l*3+2)*HK*H;
        // x1 = h @ lin1 -> fp16 (hi-only A, K'=608)
        bgemm<0,NIT1><<<gG,256>>>(p_As0, Blin1, nullptr, nullptr, nullptr, p_x1h);
        agg<<<NN, 320>>>(l);
        // m1 = ssp(msg @ l2w + l2b) -> split (2-term A)
        bgemm<1,NIT2><<<gG,256>>>(p_As1, Bl2w, l2b+(size_t)l*H, nullptr, p_As2, nullptr);
        // h = h + (m1 @ ilw + ilb); emits h split for next layer
        bgemm<2,NIT2><<<gG,256>>>(p_As2, Bilw, ilb+(size_t)l*H, p_h, p_As0, nullptr);
    }
    poolfin<<<NB, H>>>(pw, pb, out);
}